// round 11
// baseline (speedup 1.0000x reference)
#include <cuda_runtime.h>
#include <math.h>
#include <stdint.h>

#define BB 8
#define TT 2048
#define HH 1024
#define DD 64
#define NTOK (BB*TT)   // 16384

// g_q pre-scaled by log2(e)/8 so attn uses ex2 directly.
#define QSCALE 0.1803368801111204f

__device__ float g_q[NTOK*DD];
__device__ float g_k[NTOK*DD];
__device__ float g_v[NTOK*DD];
__device__ uint32_t g_wt[32 * 6144];

// split-k partial scratch: 8 batches x 68 slots x 2 tiles x (64x64) + l
__device__ float g_po[8 * 68 * 2 * 4096];
__device__ float g_pl[8 * 68 * 2 * 64];

// ---- task tables: 34 blocks per batch, each exactly 8 k-iters, <=2 tasks.
// set s (0..15) = q-tile pair {2s, 2s+1}; its k range is [0, 2s+2).
__device__ __constant__ int T0SET[34] = {
    15,15,15,15, 14,14,14, 13,13,13, 12,12,12, 11,11,11,
    10,10, 9,9, 8,8, 7,7, 6, 5, 4, 3, 14, 10, 6, 2, 13, 5};
__device__ __constant__ int T0K0[34] = {
    0,8,16,24, 0,8,16, 0,8,16, 0,8,16, 0,8,16,
    0,8, 0,8, 0,8, 0,8, 0, 0, 0, 0, 24, 16, 8, 0, 24, 8};
__device__ __constant__ int T0K1[34] = {
    8,16,24,32, 8,16,24, 8,16,24, 8,16,24, 8,16,24,
    8,16, 8,16, 8,16, 8,16, 8, 8, 8, 8, 30, 22, 14, 6, 28, 12};
__device__ __constant__ int T1SET[34] = {
    -1,-1,-1,-1, -1,-1,-1, -1,-1,-1, -1,-1,-1, -1,-1,-1,
    -1,-1, -1,-1, -1,-1, -1,-1, -1, -1, -1, -1, 12, 8, 4, 0, 9, 1};
__device__ __constant__ int T1K0[34] = {
    0,0,0,0, 0,0,0, 0,0,0, 0,0,0, 0,0,0,
    0,0, 0,0, 0,0, 0,0, 0, 0, 0, 0, 24, 16, 8, 0, 16, 0};
__device__ __constant__ int T1K1[34] = {
    0,0,0,0, 0,0,0, 0,0,0, 0,0,0, 0,0,0,
    0,0, 0,0, 0,0, 0,0, 0, 0, 0, 0, 26, 18, 10, 2, 20, 4};

// merge: per set, contributing slots (slot = bb*2 + task), -1 terminated
__device__ __constant__ int MSLOT[16][4] = {
    {63,-1,-1,-1}, {67,-1,-1,-1}, {62,-1,-1,-1}, {54,-1,-1,-1},
    {52,61,-1,-1}, {50,66,-1,-1}, {48,60,-1,-1}, {44,46,-1,-1},
    {40,42,59,-1}, {36,38,65,-1}, {32,34,58,-1}, {26,28,30,-1},
    {20,22,24,57}, {14,16,18,64}, {8,10,12,56},  {0,2,4,6}};

// ---------------------------------------------------------------------------
// helpers
// ---------------------------------------------------------------------------
__device__ __forceinline__ uint32_t f2tf(float f) {
    uint32_t r; asm("cvt.rna.tf32.f32 %0, %1;" : "=r"(r) : "f"(f)); return r;
}

__device__ __forceinline__ float ex2(float f) {
    float r; asm("ex2.approx.ftz.f32 %0, %1;" : "=f"(r) : "f"(f)); return r;
}

__device__ __forceinline__ void mma8(float c[4],
    uint32_t a0, uint32_t a1, uint32_t a2, uint32_t a3,
    uint32_t b0, uint32_t b1)
{
    asm volatile(
        "mma.sync.aligned.m16n8k8.row.col.f32.tf32.tf32.f32 "
        "{%0,%1,%2,%3}, {%4,%5,%6,%7}, {%8,%9}, {%0,%1,%2,%3};"
        : "+f"(c[0]), "+f"(c[1]), "+f"(c[2]), "+f"(c[3])
        : "r"(a0), "r"(a1), "r"(a2), "r"(a3), "r"(b0), "r"(b1));
}

__device__ __forceinline__ void ldsm4(uint32_t& r0, uint32_t& r1,
                                      uint32_t& r2, uint32_t& r3, uint32_t addr)
{
    asm volatile("ldmatrix.sync.aligned.m8n8.x4.shared.b16 {%0,%1,%2,%3}, [%4];"
        : "=r"(r0), "=r"(r1), "=r"(r2), "=r"(r3) : "r"(addr));
}

__device__ __forceinline__ void cpa16(uint32_t saddr, const void* g) {
    asm volatile("cp.async.cg.shared.global [%0], [%1], 16;" :: "r"(saddr), "l"(g));
}
#define CPA_COMMIT asm volatile("cp.async.commit_group;")
#define CPA_WAIT0  asm volatile("cp.async.wait_group 0;")
#define CPA_WAIT1  asm volatile("cp.async.wait_group 1;")

// ---------------------------------------------------------------------------
// w_prep: W -> tf32 in the pre-swizzled proj layout. 128 blocks x 256 thr.
// ---------------------------------------------------------------------------
__global__ __launch_bounds__(256) void w_prep(
    const float* __restrict__ Wk,
    const float* __restrict__ Wq,
    const float* __restrict__ Wv)
{
    const int t = threadIdx.x;
    const int chunk = blockIdx.x >> 2;
    const int n0 = (blockIdx.x & 3) * 48;
    const int k0 = chunk * 32;

    for (int task = t; task < 48 * 8; task += 256) {
        int n = n0 + (task >> 3), c4 = task & 7;
        const float* W = (n < 64) ? Wq : (n < 128) ? Wk : Wv;
        int ncol = n & 63;
        uint4 v;
        v.x = f2tf(W[(size_t)(k0 + c4 * 4 + 0) * DD + ncol]);
        v.y = f2tf(W[(size_t)(k0 + c4 * 4 + 1) * DD + ncol]);
        v.z = f2tf(W[(size_t)(k0 + c4 * 4 + 2) * DD + ncol]);
        v.w = f2tf(W[(size_t)(k0 + c4 * 4 + 3) * DD + ncol]);
        *(uint4*)&g_wt[chunk * 6144 + n * 32 + ((c4 ^ (n & 7)) << 2)] = v;
    }
}

// ---------------------------------------------------------------------------
// Fused projection (proven structure): tf32 mma, cp.async double-buffered.
// ---------------------------------------------------------------------------
#define PROJ_SMEM 57344

__global__ __launch_bounds__(256) void proj_kernel(const float* __restrict__ x)
{
    extern __shared__ uint32_t psm[];
    const uint32_t sb = (uint32_t)__cvta_generic_to_shared(psm);

    const int t    = threadIdx.x;
    const int lane = t & 31;
    const int warp = t >> 5;
    const int g    = lane >> 2;
    const int tig  = lane & 3;
    const int warpM = warp & 3;
    const int warpN = warp >> 2;
    const int row0 = blockIdx.x * 128;
    const int nh   = blockIdx.y;

    float acc[2][6][4];
    #pragma unroll
    for (int a = 0; a < 2; a++)
        #pragma unroll
        for (int j = 0; j < 6; j++)
            #pragma unroll
            for (int e = 0; e < 4; e++) acc[a][j][e] = 0.f;

    const int arow0 = warpM * 32 + ((lane >> 3) & 1) * 8 + (lane & 7);
    const int a_kh  = (lane >> 4) & 1;
    const int brow0 = warpN * 48 + ((lane >> 4) & 1) * 8 + (lane & 7);
    const int k_kh  = (lane >> 3) & 1;

    auto load_chunk = [&](int c) {
        uint32_t xb = sb + (c & 1) * 16384;
        const float* xsrc = x + (size_t)row0 * HH + c * 32;
        #pragma unroll
        for (int i = 0; i < 4; i++) {
            int task = t + i * 256;
            int r = task >> 3, c4 = task & 7;
            cpa16(xb + r * 128 + ((c4 ^ (r & 7)) << 4),
                  xsrc + (size_t)r * HH + c4 * 4);
        }
        uint32_t wb = sb + 32768 + (c & 1) * 12288;
        const uint32_t* wsrc = g_wt + c * 6144 + nh * 3072;
        #pragma unroll
        for (int i = 0; i < 3; i++) {
            int task = t + i * 256;
            cpa16(wb + task * 16, wsrc + task * 4);
        }
    };

    load_chunk(0);
    CPA_COMMIT;

    for (int c = 0; c < 32; c++) {
        if (c + 1 < 32) {
            load_chunk(c + 1);
            CPA_COMMIT;
            CPA_WAIT1;
        } else {
            CPA_WAIT0;
        }
        __syncthreads();

        const uint32_t xb = sb + (c & 1) * 16384;
        const uint32_t wb = sb + 32768 + (c & 1) * 12288;

        #pragma unroll
        for (int ks = 0; ks < 4; ks++) {
            uint32_t a[2][4];
            #pragma unroll
            for (int mt = 0; mt < 2; mt++) {
                int ar = arow0 + mt * 16;
                ldsm4(a[mt][0], a[mt][1], a[mt][2], a[mt][3],
                      xb + ar * 128 + (((2 * ks + a_kh) ^ (ar & 7)) << 4));
            }
            #pragma unroll
            for (int p = 0; p < 3; p++) {
                int br = brow0 + p * 16;
                uint32_t b0, b1, b2, b3;
                ldsm4(b0, b1, b2, b3,
                      wb + br * 128 + (((2 * ks + k_kh) ^ (br & 7)) << 4));
                mma8(acc[0][2 * p],     a[0][0], a[0][1], a[0][2], a[0][3], b0, b1);
                mma8(acc[0][2 * p + 1], a[0][0], a[0][1], a[0][2], a[0][3], b2, b3);
                mma8(acc[1][2 * p],     a[1][0], a[1][1], a[1][2], a[1][3], b0, b1);
                mma8(acc[1][2 * p + 1], a[1][0], a[1][1], a[1][2], a[1][3], b2, b3);
            }
        }
        __syncthreads();
    }

    #pragma unroll
    for (int mt = 0; mt < 2; mt++) {
        int r = row0 + warpM * 32 + mt * 16 + g;
        #pragma unroll
        for (int j = 0; j < 6; j++) {
            int nb = nh * 96 + warpN * 48 + j * 8;
            float* o = (nb < 64) ? g_q : (nb < 128) ? g_k : g_v;
            float sc = (nb < 64) ? QSCALE : 1.0f;
            int cc = (nb & 63) + 2 * tig;
            *(float2*)&o[(size_t)r * DD + cc] = make_float2(
                __uint_as_float(f2tf(acc[mt][j][0] * sc)),
                __uint_as_float(f2tf(acc[mt][j][1] * sc)));
            *(float2*)&o[(size_t)(r + 8) * DD + cc] = make_float2(
                __uint_as_float(f2tf(acc[mt][j][2] * sc)),
                __uint_as_float(f2tf(acc[mt][j][3] * sc)));
        }
    }
}

// ---------------------------------------------------------------------------
// Attention: 272 blocks x 256 threads (2 groups of 128), 2 blocks/SM.
// Groups share the K/V tile stream (q-tiles 2s, 2s+1). Exactly 8 k-iters
// per block (<=2 tasks). Single-buffered K and Vraw: prefetch for iter+1 is
// issued after the mid-iter sync (PV phase covers the gmem latency).
// smem words: qs[g]@g*4096, k@8192, vraw@12288, vt@16384, ps[g]@20480+g*4096.
// Total 28672 words = 112KB -> 2 blocks/SM.
// ---------------------------------------------------------------------------
#define ATTN_SMEM 114688

__device__ __forceinline__ void cpa_tile(uint32_t sbase_b, const float* gsrc, int lt) {
    #pragma unroll
    for (int i = 0; i < 8; i++) {
        int task = lt + i * 128;
        int r = task >> 4, c4 = task & 15;
        cpa16(sbase_b + r * 256 + ((c4 ^ (r & 7)) << 4), gsrc + r * 64 + c4 * 4);
    }
}

__device__ __forceinline__ void cpa_tile256(uint32_t sbase_b, const float* gsrc, int tid) {
    #pragma unroll
    for (int i = 0; i < 4; i++) {
        int task = tid + i * 256;
        int r = task >> 4, c4 = task & 15;
        cpa16(sbase_b + r * 256 + ((c4 ^ (r & 7)) << 4), gsrc + r * 64 + c4 * 4);
    }
}

__global__ __launch_bounds__(256, 2) void attn_kernel()
{
    extern __shared__ uint32_t sm[];
    const uint32_t base = (uint32_t)__cvta_generic_to_shared(sm);

    const int tid   = threadIdx.x;
    const int group = tid >> 7;
    const int lt    = tid & 127;
    const int lane  = tid & 31;
    const int warpg = lt >> 5;
    const int g     = lane >> 2;
    const int tig   = lane & 3;
    const int wr    = warpg * 16;
    const int batch = blockIdx.x / 34;
    const int bb    = blockIdx.x % 34;

    const uint32_t qb = base + group * 16384;      // qs bytes
    // k @ byte 32768, vraw @ 49152, vt @ 65536, ps @ 81920 + group*16384

    // ldmatrix per-thread constants
    const int qrow = wr + ((lane >> 3) & 1) * 8 + (lane & 7);
    const uint32_t qab = qb + qrow * 256;
    const uint32_t pab = base + 81920 + group * 16384 + qrow * 256;
    const int q_kh = (lane >> 4) & 1, q_sw = qrow & 7;
    const int krlo = ((lane >> 4) & 1) * 8 + (lane & 7);
    const int k_kh = (lane >> 3) & 1;
    const uint32_t kab_c = base + 32768;
    const uint32_t vtb   = base + 65536;

    // transpose task constants (2 tasks per thread: tau = tid, tid+256)
    const size_t kvoff = (size_t)batch * TT * DD;

    #pragma unroll 1
    for (int task = 0; task < 2; task++) {
        int set, k0t, k1t;
        if (task == 0) { set = T0SET[bb]; k0t = T0K0[bb]; k1t = T0K1[bb]; }
        else           { set = T1SET[bb]; k0t = T1K0[bb]; k1t = T1K1[bb];
                         if (set < 0) break; }
        const int qt   = set * 2 + group;
        const int slot = bb * 2 + task;

        __syncthreads();   // protect buffers from previous task's consumers

        // prologue: own Q + shared K/Vraw(k0t)
        cpa_tile(qb, g_q + kvoff + (size_t)qt * 64 * DD, lt);
        cpa_tile256(base + 32768, g_k + kvoff + (size_t)k0t * 64 * DD, tid);
        cpa_tile256(base + 49152, g_v + kvoff + (size_t)k0t * 64 * DD, tid);
        CPA_COMMIT;

        float l0 = 0.f, l1 = 0.f;
        float o[8][4];
        #pragma unroll
        for (int nt = 0; nt < 8; nt++)
            #pragma unroll
            for (int e = 0; e < 4; e++) o[nt][e] = 0.f;

        for (int kt = k0t; kt < k1t; kt++) {
            CPA_WAIT0;
            __syncthreads();   // K/Vraw(kt), Q ready; prev PV reads of vt/ps done

            // ---- transpose Vraw -> vt (2 tasks per thread) ----
            #pragma unroll
            for (int i = 0; i < 2; i++) {
                int tau = tid + i * 256;
                int tpc = tau & 31, tj = tau >> 5;     // tj 0..15
                int tcc = ((tpc >> 2) << 3) | (tpc & 3);
                int c4l = tcc >> 2, c4h = c4l + 1;
                int tsl = c4l ^ (c4l >> 3);
                int tsh = c4h ^ (c4h >> 3);
                int te3 = tcc & 3;
                float4 lo = *(const float4*)&sm[12288 + tcc * 64 + ((tj ^ (tcc & 7)) << 2)];
                float4 hi = *(const float4*)&sm[12288 + (tcc + 4) * 64 + ((tj ^ ((tcc + 4) & 7)) << 2)];
                uint32_t* vtw = sm + 16384;
                const float* lp = (const float*)&lo;
                const float* hp = (const float*)&hi;
                #pragma unroll
                for (int e = 0; e < 4; e++) {
                    int r = 4 * tj + e;
                    vtw[r * 64 + ((tsl ^ (r & 7)) << 2) + te3] = __float_as_uint(lp[e]);
                    vtw[r * 64 + ((tsh ^ (r & 7)) << 2) + te3] = __float_as_uint(hp[e]);
                }
            }

            // ---- S = Q K^T (Q pre-scaled by log2e/8) ----
            float s[8][4];
            #pragma unroll
            for (int nt = 0; nt < 8; nt++)
                #pragma unroll
                for (int e = 0; e < 4; e++) s[nt][e] = 0.f;

            #pragma unroll
            for (int ksx = 0; ksx < 8; ksx++) {
                uint32_t a0, a1, a2, a3;
                ldsm4(a0, a1, a2, a3, qab + (((2 * ksx + q_kh) ^ q_sw) << 4));
                #pragma unroll
                for (int p = 0; p < 4; p++) {
                    int kr = p * 16 + krlo;
                    uint32_t b0, b1, b2, b3;
                    ldsm4(b0, b1, b2, b3,
                          kab_c + kr * 256 + (((2 * ksx + k_kh) ^ (kr & 7)) << 4));
                    mma8(s[2 * p],     a0, a1, a2, a3, b0, b1);
                    mma8(s[2 * p + 1], a0, a1, a2, a3, b2, b3);
                }
            }

            // ---- mask (only when kt >= qt) + exp -> ps ----
            const int r0 = wr + g, r1 = wr + g + 8;
            uint32_t* psw = sm + 20480 + group * 4096;
            const int sw0 = r0 & 7, sw1 = r1 & 7;
            if (kt >= qt) {
                const int gr0 = (qt << 6) + r0, gr1 = (qt << 6) + r1;
                #pragma unroll
                for (int nt = 0; nt < 8; nt++) {
                    int gc = (kt << 6) + nt * 8 + 2 * tig;
                    if (gc     > gr0) s[nt][0] = -INFINITY;
                    if (gc + 1 > gr0) s[nt][1] = -INFINITY;
                    if (gc     > gr1) s[nt][2] = -INFINITY;
                    if (gc + 1 > gr1) s[nt][3] = -INFINITY;
                }
            }
            #pragma unroll
            for (int nt = 0; nt < 8; nt++) {
                int c0 = nt * 8 + 2 * tig;
                float p0 = ex2(s[nt][0]);
                float p1 = ex2(s[nt][1]);
                float p2 = ex2(s[nt][2]);
                float p3 = ex2(s[nt][3]);
                l0 += p0 + p1; l1 += p2 + p3;
                int c4 = c0 >> 2, e3 = c0 & 3;
                ((uint2*)psw)[(r0 * 64 + ((c4 ^ sw0) << 2) + e3) >> 1] =
                    make_uint2(f2tf(p0), f2tf(p1));
                ((uint2*)psw)[(r1 * 64 + ((c4 ^ sw1) << 2) + e3) >> 1] =
                    make_uint2(f2tf(p2), f2tf(p3));
            }

            __syncthreads();   // vt + ps visible; K & vraw fully consumed

            // prefetch next K/V into the (now free) single buffers
            if (kt + 1 < k1t) {
                cpa_tile256(base + 32768, g_k + kvoff + (size_t)(kt + 1) * 64 * DD, tid);
                cpa_tile256(base + 49152, g_v + kvoff + (size_t)(kt + 1) * 64 * DD, tid);
                CPA_COMMIT;
            }

            // ---- O += P V ----
            #pragma unroll
            for (int ksx = 0; ksx < 8; ksx++) {
                uint32_t a0, a1, a2, a3;
                ldsm4(a0, a1, a2, a3, pab + (((2 * ksx + q_kh) ^ q_sw) << 4));
                const int chv = (2 * ksx + k_kh) ^ (ksx >= 4 ? 1 : 0);
                #pragma unroll
                for (int p = 0; p < 4; p++) {
                    int vr = p * 16 + krlo;
                    uint32_t b0, b1, b2, b3;
                    ldsm4(b0, b1, b2, b3, vtb + vr * 256 + ((chv ^ (vr & 7)) << 4));
                    mma8(o[2 * p],     a0, a1, a2, a3, b0, b1);
                    mma8(o[2 * p + 1], a0, a1, a2, a3, b2, b3);
                }
            }
        }

        // ---- epilogue: write unnormalized partials ----
        l0 += __shfl_xor_sync(0xffffffffu, l0, 1);
        l0 += __shfl_xor_sync(0xffffffffu, l0, 2);
        l1 += __shfl_xor_sync(0xffffffffu, l1, 1);
        l1 += __shfl_xor_sync(0xffffffffu, l1, 2);

        const int sbase = (batch * 68 + slot) * 2 + group;
        float* po = g_po + (size_t)sbase * 4096;
        const int r0 = wr + g, r1 = wr + g + 8;
        #pragma unroll
        for (int nt = 0; nt < 8; nt++) {
            int cc = nt * 8 + 2 * tig;
            *(float2*)&po[r0 * 64 + cc] = make_float2(o[nt][0], o[nt][1]);
            *(float2*)&po[r1 * 64 + cc] = make_float2(o[nt][2], o[nt][3]);
        }
        if (tig == 0) {
            g_pl[sbase * 64 + r0] = l0;
            g_pl[sbase * 64 + r1] = l1;
        }
    }
}

// ---------------------------------------------------------------------------
// merge: out[tile] = sum(O partials) / sum(l partials).
// 1024 blocks x 256 threads, one float4 per thread.
// ---------------------------------------------------------------------------
__global__ __launch_bounds__(256) void merge_kernel(float* __restrict__ out)
{
    const int tile  = blockIdx.x >> 2;          // 0..255
    const int batch = tile >> 5;
    const int qt    = tile & 31;
    const int set   = qt >> 1;
    const int gg    = qt & 1;

    const int i4  = (blockIdx.x & 3) * 256 + threadIdx.x;   // 0..1023
    const int row = i4 >> 4;
    const int d0  = (i4 & 15) << 2;

    float4 os = make_float4(0.f, 0.f, 0.f, 0.f);
    float ls = 0.f;
    #pragma unroll
    for (int i = 0; i < 4; i++) {
        int s = MSLOT[set][i];
        if (s >= 0) {
            int sbase = (batch * 68 + s) * 2 + gg;
            float4 v = *(const float4*)&g_po[(size_t)sbase * 4096 + row * 64 + d0];
            os.x += v.x; os.y += v.y; os.z += v.z; os.w += v.w;
            ls += g_pl[sbase * 64 + row];
        }
    }
    float inv = 1.f / ls;
    float4 w = make_float4(os.x * inv, os.y * inv, os.z * inv, os.w * inv);
    *(float4*)&out[((size_t)(batch * TT + qt * 64 + row)) * DD + d0] = w;
}

// ---------------------------------------------------------------------------
extern "C" void kernel_launch(void* const* d_in, const int* in_sizes, int n_in,
                              void* d_out, int out_size)
{
    const float* x  = (const float*)d_in[0];
    const float* Wk = (const float*)d_in[1];
    const float* Wq = (const float*)d_in[2];
    const float* Wv = (const float*)d_in[3];
    float* out = (float*)d_out;

    cudaFuncSetAttribute(proj_kernel,
                         cudaFuncAttributeMaxDynamicSharedMemorySize, PROJ_SMEM);
    cudaFuncSetAttribute(attn_kernel,
                         cudaFuncAttributeMaxDynamicSharedMemorySize, ATTN_SMEM);

    w_prep<<<128, 256>>>(Wk, Wq, Wv);
    proj_kernel<<<dim3(128, 2), 256, PROJ_SMEM>>>(x);
    attn_kernel<<<8 * 34, 256, ATTN_SMEM>>>();
    merge_kernel<<<1024, 256>>>(out);
}

// round 13
// speedup vs baseline: 1.1891x; 1.1891x over previous
#include <cuda_runtime.h>
#include <math.h>
#include <stdint.h>

#define BB 8
#define TT 2048
#define HH 1024
#define DD 64
#define NTOK (BB*TT)   // 16384

// g_q pre-scaled by log2(e)/8 so attn uses ex2 directly.
#define QSCALE 0.1803368801111204f

__device__ float g_q[NTOK*DD];
__device__ float g_k[NTOK*DD];
__device__ uint32_t g_vb[NTOK*32];     // V as packed fp16x2, rows of 32 words
__device__ uint32_t g_wt[32 * 6144];

// split-k partial scratch: 8 batches x 68 slots x 2 tiles x (64x64) + l
__device__ float g_po[8 * 68 * 2 * 4096];
__device__ float g_pl[8 * 68 * 2 * 64];

// ---- task tables: 34 blocks per batch, each exactly 8 k-iters, <=2 tasks.
// set s (0..15) = q-tile pair {2s, 2s+1}; its k range is [0, 2s+2).
__device__ __constant__ int T0SET[34] = {
    15,15,15,15, 14,14,14, 13,13,13, 12,12,12, 11,11,11,
    10,10, 9,9, 8,8, 7,7, 6, 5, 4, 3, 14, 10, 6, 2, 13, 5};
__device__ __constant__ int T0K0[34] = {
    0,8,16,24, 0,8,16, 0,8,16, 0,8,16, 0,8,16,
    0,8, 0,8, 0,8, 0,8, 0, 0, 0, 0, 24, 16, 8, 0, 24, 8};
__device__ __constant__ int T0K1[34] = {
    8,16,24,32, 8,16,24, 8,16,24, 8,16,24, 8,16,24,
    8,16, 8,16, 8,16, 8,16, 8, 8, 8, 8, 30, 22, 14, 6, 28, 12};
__device__ __constant__ int T1SET[34] = {
    -1,-1,-1,-1, -1,-1,-1, -1,-1,-1, -1,-1,-1, -1,-1,-1,
    -1,-1, -1,-1, -1,-1, -1,-1, -1, -1, -1, -1, 12, 8, 4, 0, 9, 1};
__device__ __constant__ int T1K0[34] = {
    0,0,0,0, 0,0,0, 0,0,0, 0,0,0, 0,0,0,
    0,0, 0,0, 0,0, 0,0, 0, 0, 0, 0, 24, 16, 8, 0, 16, 0};
__device__ __constant__ int T1K1[34] = {
    0,0,0,0, 0,0,0, 0,0,0, 0,0,0, 0,0,0,
    0,0, 0,0, 0,0, 0,0, 0, 0, 0, 0, 26, 18, 10, 2, 20, 4};

__device__ __constant__ int MSLOT[16][4] = {
    {63,-1,-1,-1}, {67,-1,-1,-1}, {62,-1,-1,-1}, {54,-1,-1,-1},
    {52,61,-1,-1}, {50,66,-1,-1}, {48,60,-1,-1}, {44,46,-1,-1},
    {40,42,59,-1}, {36,38,65,-1}, {32,34,58,-1}, {26,28,30,-1},
    {20,22,24,57}, {14,16,18,64}, {8,10,12,56},  {0,2,4,6}};

// ---------------------------------------------------------------------------
// helpers
// ---------------------------------------------------------------------------
__device__ __forceinline__ uint32_t f2tf(float f) {
    uint32_t r; asm("cvt.rna.tf32.f32 %0, %1;" : "=r"(r) : "f"(f)); return r;
}

__device__ __forceinline__ float ex2(float f) {
    float r; asm("ex2.approx.ftz.f32 %0, %1;" : "=f"(r) : "f"(f)); return r;
}

__device__ __forceinline__ uint32_t h2(float lo, float hi) {
    uint32_t r; asm("cvt.rn.f16x2.f32 %0, %1, %2;" : "=r"(r) : "f"(hi), "f"(lo));
    return r;
}

__device__ __forceinline__ void mma8(float c[4],
    uint32_t a0, uint32_t a1, uint32_t a2, uint32_t a3,
    uint32_t b0, uint32_t b1)
{
    asm volatile(
        "mma.sync.aligned.m16n8k8.row.col.f32.tf32.tf32.f32 "
        "{%0,%1,%2,%3}, {%4,%5,%6,%7}, {%8,%9}, {%0,%1,%2,%3};"
        : "+f"(c[0]), "+f"(c[1]), "+f"(c[2]), "+f"(c[3])
        : "r"(a0), "r"(a1), "r"(a2), "r"(a3), "r"(b0), "r"(b1));
}

__device__ __forceinline__ void mma16(float c[4],
    uint32_t a0, uint32_t a1, uint32_t a2, uint32_t a3,
    uint32_t b0, uint32_t b1)
{
    asm volatile(
        "mma.sync.aligned.m16n8k16.row.col.f32.f16.f16.f32 "
        "{%0,%1,%2,%3}, {%4,%5,%6,%7}, {%8,%9}, {%0,%1,%2,%3};"
        : "+f"(c[0]), "+f"(c[1]), "+f"(c[2]), "+f"(c[3])
        : "r"(a0), "r"(a1), "r"(a2), "r"(a3), "r"(b0), "r"(b1));
}

__device__ __forceinline__ void ldsm4(uint32_t& r0, uint32_t& r1,
                                      uint32_t& r2, uint32_t& r3, uint32_t addr)
{
    asm volatile("ldmatrix.sync.aligned.m8n8.x4.shared.b16 {%0,%1,%2,%3}, [%4];"
        : "=r"(r0), "=r"(r1), "=r"(r2), "=r"(r3) : "r"(addr));
}

__device__ __forceinline__ void ldsm4t(uint32_t& r0, uint32_t& r1,
                                       uint32_t& r2, uint32_t& r3, uint32_t addr)
{
    asm volatile("ldmatrix.sync.aligned.m8n8.x4.trans.shared.b16 {%0,%1,%2,%3}, [%4];"
        : "=r"(r0), "=r"(r1), "=r"(r2), "=r"(r3) : "r"(addr));
}

__device__ __forceinline__ void cpa16(uint32_t saddr, const void* g) {
    asm volatile("cp.async.cg.shared.global [%0], [%1], 16;" :: "r"(saddr), "l"(g));
}
#define CPA_COMMIT asm volatile("cp.async.commit_group;")
#define CPA_WAIT0  asm volatile("cp.async.wait_group 0;")
#define CPA_WAIT1  asm volatile("cp.async.wait_group 1;")

// ---------------------------------------------------------------------------
// w_prep: W -> tf32 in the pre-swizzled proj layout. 128 blocks x 256 thr.
// ---------------------------------------------------------------------------
__global__ __launch_bounds__(256) void w_prep(
    const float* __restrict__ Wk,
    const float* __restrict__ Wq,
    const float* __restrict__ Wv)
{
    const int t = threadIdx.x;
    const int chunk = blockIdx.x >> 2;
    const int n0 = (blockIdx.x & 3) * 48;
    const int k0 = chunk * 32;

    for (int task = t; task < 48 * 8; task += 256) {
        int n = n0 + (task >> 3), c4 = task & 7;
        const float* W = (n < 64) ? Wq : (n < 128) ? Wk : Wv;
        int ncol = n & 63;
        uint4 v;
        v.x = f2tf(W[(size_t)(k0 + c4 * 4 + 0) * DD + ncol]);
        v.y = f2tf(W[(size_t)(k0 + c4 * 4 + 1) * DD + ncol]);
        v.z = f2tf(W[(size_t)(k0 + c4 * 4 + 2) * DD + ncol]);
        v.w = f2tf(W[(size_t)(k0 + c4 * 4 + 3) * DD + ncol]);
        *(uint4*)&g_wt[chunk * 6144 + n * 32 + ((c4 ^ (n & 7)) << 2)] = v;
    }
}

// ---------------------------------------------------------------------------
// Fused projection: tf32 mma, cp.async double-buffered. q scaled by QSCALE;
// v written as packed fp16x2 (g_vb).
// ---------------------------------------------------------------------------
#define PROJ_SMEM 57344

__global__ __launch_bounds__(256) void proj_kernel(const float* __restrict__ x)
{
    extern __shared__ uint32_t psm[];
    const uint32_t sb = (uint32_t)__cvta_generic_to_shared(psm);

    const int t    = threadIdx.x;
    const int lane = t & 31;
    const int warp = t >> 5;
    const int g    = lane >> 2;
    const int tig  = lane & 3;
    const int warpM = warp & 3;
    const int warpN = warp >> 2;
    const int row0 = blockIdx.x * 128;
    const int nh   = blockIdx.y;

    float acc[2][6][4];
    #pragma unroll
    for (int a = 0; a < 2; a++)
        #pragma unroll
        for (int j = 0; j < 6; j++)
            #pragma unroll
            for (int e = 0; e < 4; e++) acc[a][j][e] = 0.f;

    const int arow0 = warpM * 32 + ((lane >> 3) & 1) * 8 + (lane & 7);
    const int a_kh  = (lane >> 4) & 1;
    const int brow0 = warpN * 48 + ((lane >> 4) & 1) * 8 + (lane & 7);
    const int k_kh  = (lane >> 3) & 1;

    auto load_chunk = [&](int c) {
        uint32_t xb = sb + (c & 1) * 16384;
        const float* xsrc = x + (size_t)row0 * HH + c * 32;
        #pragma unroll
        for (int i = 0; i < 4; i++) {
            int task = t + i * 256;
            int r = task >> 3, c4 = task & 7;
            cpa16(xb + r * 128 + ((c4 ^ (r & 7)) << 4),
                  xsrc + (size_t)r * HH + c4 * 4);
        }
        uint32_t wb = sb + 32768 + (c & 1) * 12288;
        const uint32_t* wsrc = g_wt + c * 6144 + nh * 3072;
        #pragma unroll
        for (int i = 0; i < 3; i++) {
            int task = t + i * 256;
            cpa16(wb + task * 16, wsrc + task * 4);
        }
    };

    load_chunk(0);
    CPA_COMMIT;

    for (int c = 0; c < 32; c++) {
        if (c + 1 < 32) {
            load_chunk(c + 1);
            CPA_COMMIT;
            CPA_WAIT1;
        } else {
            CPA_WAIT0;
        }
        __syncthreads();

        const uint32_t xb = sb + (c & 1) * 16384;
        const uint32_t wb = sb + 32768 + (c & 1) * 12288;

        #pragma unroll
        for (int ks = 0; ks < 4; ks++) {
            uint32_t a[2][4];
            #pragma unroll
            for (int mt = 0; mt < 2; mt++) {
                int ar = arow0 + mt * 16;
                ldsm4(a[mt][0], a[mt][1], a[mt][2], a[mt][3],
                      xb + ar * 128 + (((2 * ks + a_kh) ^ (ar & 7)) << 4));
            }
            #pragma unroll
            for (int p = 0; p < 3; p++) {
                int br = brow0 + p * 16;
                uint32_t b0, b1, b2, b3;
                ldsm4(b0, b1, b2, b3,
                      wb + br * 128 + (((2 * ks + k_kh) ^ (br & 7)) << 4));
                mma8(acc[0][2 * p],     a[0][0], a[0][1], a[0][2], a[0][3], b0, b1);
                mma8(acc[0][2 * p + 1], a[0][0], a[0][1], a[0][2], a[0][3], b2, b3);
                mma8(acc[1][2 * p],     a[1][0], a[1][1], a[1][2], a[1][3], b0, b1);
                mma8(acc[1][2 * p + 1], a[1][0], a[1][1], a[1][2], a[1][3], b2, b3);
            }
        }
        __syncthreads();
    }

    #pragma unroll
    for (int mt = 0; mt < 2; mt++) {
        int r = row0 + warpM * 32 + mt * 16 + g;
        #pragma unroll
        for (int j = 0; j < 6; j++) {
            int nb = nh * 96 + warpN * 48 + j * 8;
            int cc = (nb & 63) + 2 * tig;
            if (nb < 128) {
                float* o = (nb < 64) ? g_q : g_k;
                float sc = (nb < 64) ? QSCALE : 1.0f;
                *(float2*)&o[(size_t)r * DD + cc] = make_float2(
                    __uint_as_float(f2tf(acc[mt][j][0] * sc)),
                    __uint_as_float(f2tf(acc[mt][j][1] * sc)));
                *(float2*)&o[(size_t)(r + 8) * DD + cc] = make_float2(
                    __uint_as_float(f2tf(acc[mt][j][2] * sc)),
                    __uint_as_float(f2tf(acc[mt][j][3] * sc)));
            } else {
                int w = ((nb & 63) >> 1) + tig;
                g_vb[(size_t)r       * 32 + w] = h2(acc[mt][j][0], acc[mt][j][1]);
                g_vb[(size_t)(r + 8) * 32 + w] = h2(acc[mt][j][2], acc[mt][j][3]);
            }
        }
    }
}

// ---------------------------------------------------------------------------
// Attention: 272 blocks x 256 threads (2 groups), 2 blocks/SM, 8 k-iters each.
// S = QK^T in tf32 mma; PV in fp16 m16n8k16 with V fed straight from raw
// fp16 smem via ldmatrix.trans (no transpose phase, no vt buffer).
// smem bytes: qs[g]@g*16384 (32K), K dbl @32768 (32K), Vraw dbl @65536 (16K),
// ps fp16 [g] @81920+g*8192 (16K). Total 96KB -> 2 blocks/SM.
// ---------------------------------------------------------------------------
#define ATTN_SMEM 98304

__device__ __forceinline__ void cpa_tile(uint32_t sbase_b, const float* gsrc, int lt) {
    #pragma unroll
    for (int i = 0; i < 8; i++) {
        int task = lt + i * 128;
        int r = task >> 4, c4 = task & 15;
        cpa16(sbase_b + r * 256 + ((c4 ^ (r & 7)) << 4), gsrc + r * 64 + c4 * 4);
    }
}

__device__ __forceinline__ void cpa_tile256(uint32_t sbase_b, const float* gsrc, int tid) {
    #pragma unroll
    for (int i = 0; i < 4; i++) {
        int task = tid + i * 256;
        int r = task >> 4, c4 = task & 15;
        cpa16(sbase_b + r * 256 + ((c4 ^ (r & 7)) << 4), gsrc + r * 64 + c4 * 4);
    }
}

// V tile: 64 rows x 128B (fp16), 512 16B-chunks, 2 per thread
__device__ __forceinline__ void cpa_vtile(uint32_t sbase_b, const uint32_t* gsrc, int tid) {
    #pragma unroll
    for (int i = 0; i < 2; i++) {
        int task = tid + i * 256;
        int r = task >> 3, c4 = task & 7;
        cpa16(sbase_b + r * 128 + ((c4 ^ (r & 7)) << 4), gsrc + r * 32 + c4 * 4);
    }
}

__global__ __launch_bounds__(256, 2) void attn_kernel()
{
    extern __shared__ uint32_t sm[];
    const uint32_t base = (uint32_t)__cvta_generic_to_shared(sm);

    const int tid   = threadIdx.x;
    const int group = tid >> 7;
    const int lt    = tid & 127;
    const int lane  = tid & 31;
    const int warpg = lt >> 5;
    const int g     = lane >> 2;
    const int tig   = lane & 3;
    const int wr    = warpg * 16;
    const int batch = blockIdx.x / 34;
    const int bb    = blockIdx.x % 34;

    const uint32_t qb = base + group * 16384;

    // ldmatrix per-thread constants
    const int qrow = wr + ((lane >> 3) & 1) * 8 + (lane & 7);
    const uint32_t qab = qb + qrow * 256;                    // Q rows 256B
    const uint32_t pab = base + 81920 + group * 8192 + qrow * 128;  // P rows 128B
    const int q_kh = (lane >> 4) & 1, q_sw = qrow & 7;
    const int krlo = ((lane >> 4) & 1) * 8 + (lane & 7);
    const int k_kh = (lane >> 3) & 1;
    // V (trans) per-lane row-within-16 and n-pair half
    const int vrlo = (lane & 7) + ((lane >> 3) & 1) * 8;     // 0..15
    const int v_nh = (lane >> 4) & 1;
    const int v_sw = vrlo & 7;

    const size_t kvoff  = (size_t)batch * TT * DD;
    const size_t kvoffv = (size_t)batch * TT * 32;

    #pragma unroll 1
    for (int task = 0; task < 2; task++) {
        int set, k0t, k1t;
        if (task == 0) { set = T0SET[bb]; k0t = T0K0[bb]; k1t = T0K1[bb]; }
        else           { set = T1SET[bb]; k0t = T1K0[bb]; k1t = T1K1[bb];
                         if (set < 0) break; }
        const int qt   = set * 2 + group;
        const int slot = bb * 2 + task;

        __syncthreads();   // qs consumers from previous task done

        // prologue: own Q + shared K/V (k0t)
        cpa_tile(qb, g_q + kvoff + (size_t)qt * 64 * DD, lt);
        cpa_tile256(base + 32768 + (k0t & 1) * 16384,
                    g_k + kvoff + (size_t)k0t * 64 * DD, tid);
        cpa_vtile(base + 65536 + (k0t & 1) * 8192,
                  g_vb + kvoffv + (size_t)k0t * 64 * 32, tid);
        CPA_COMMIT;

        float l0 = 0.f, l1 = 0.f;
        float o[8][4];
        #pragma unroll
        for (int nt = 0; nt < 8; nt++)
            #pragma unroll
            for (int e = 0; e < 4; e++) o[nt][e] = 0.f;

        for (int kt = k0t; kt < k1t; kt++) {
            CPA_WAIT0;
            __syncthreads();   // K/V(kt), Q visible; prev iter reads done

            if (kt + 1 < k1t) {
                cpa_tile256(base + 32768 + ((kt + 1) & 1) * 16384,
                            g_k + kvoff + (size_t)(kt + 1) * 64 * DD, tid);
                cpa_vtile(base + 65536 + ((kt + 1) & 1) * 8192,
                          g_vb + kvoffv + (size_t)(kt + 1) * 64 * 32, tid);
                CPA_COMMIT;
            }

            const uint32_t kab = base + 32768 + (kt & 1) * 16384;
            const uint32_t vab = base + 65536 + (kt & 1) * 8192;

            // ---- S = Q K^T (tf32; Q pre-scaled by log2e/8) ----
            float s[8][4];
            #pragma unroll
            for (int nt = 0; nt < 8; nt++)
                #pragma unroll
                for (int e = 0; e < 4; e++) s[nt][e] = 0.f;

            #pragma unroll
            for (int ksx = 0; ksx < 8; ksx++) {
                uint32_t a0, a1, a2, a3;
                ldsm4(a0, a1, a2, a3, qab + (((2 * ksx + q_kh) ^ q_sw) << 4));
                #pragma unroll
                for (int p = 0; p < 4; p++) {
                    int kr = p * 16 + krlo;
                    uint32_t b0, b1, b2, b3;
                    ldsm4(b0, b1, b2, b3,
                          kab + kr * 256 + (((2 * ksx + k_kh) ^ (kr & 7)) << 4));
                    mma8(s[2 * p],     a0, a1, a2, a3, b0, b1);
                    mma8(s[2 * p + 1], a0, a1, a2, a3, b2, b3);
                }
            }

            // ---- mask (only when kt >= qt) + exp -> ps (fp16x2) ----
            const int r0 = wr + g, r1 = wr + g + 8;
            uint32_t* psw = sm + 20480 + group * 2048;
            const int sw0 = r0 & 7, sw1 = r1 & 7;
            if (kt >= qt) {
                const int gr0 = (qt << 6) + r0, gr1 = (qt << 6) + r1;
                #pragma unroll
                for (int nt = 0; nt < 8; nt++) {
                    int gc = (kt << 6) + nt * 8 + 2 * tig;
                    if (gc     > gr0) s[nt][0] = -INFINITY;
                    if (gc + 1 > gr0) s[nt][1] = -INFINITY;
                    if (gc     > gr1) s[nt][2] = -INFINITY;
                    if (gc + 1 > gr1) s[nt][3] = -INFINITY;
                }
            }
            #pragma unroll
            for (int nt = 0; nt < 8; nt++) {
                float p0 = ex2(s[nt][0]);
                float p1 = ex2(s[nt][1]);
                float p2 = ex2(s[nt][2]);
                float p3 = ex2(s[nt][3]);
                l0 += p0 + p1; l1 += p2 + p3;
                psw[r0 * 32 + ((nt ^ sw0) << 2) + tig] = h2(p0, p1);
                psw[r1 * 32 + ((nt ^ sw1) << 2) + tig] = h2(p2, p3);
            }
            __syncwarp();   // ps rows wr..wr+15 are warp-local

            // ---- O += P V (fp16 m16n8k16; B via ldmatrix.trans on raw V) ----
            #pragma unroll
            for (int kb = 0; kb < 4; kb++) {
                uint32_t a0, a1, a2, a3;
                ldsm4(a0, a1, a2, a3, pab + (((2 * kb + q_kh) ^ q_sw) << 4));
                int vrow = kb * 16 + vrlo;
                #pragma unroll
                for (int nbp = 0; nbp < 4; nbp++) {
                    uint32_t b0, b1, b2, b3;
                    int nbx = nbp * 2 + v_nh;
                    ldsm4t(b0, b1, b2, b3,
                           vab + vrow * 128 + ((nbx ^ v_sw) << 4));
                    mma16(o[nbp * 2],     a0, a1, a2, a3, b0, b1);
                    mma16(o[nbp * 2 + 1], a0, a1, a2, a3, b2, b3);
                }
            }
        }

        // ---- epilogue: write unnormalized partials ----
        l0 += __shfl_xor_sync(0xffffffffu, l0, 1);
        l0 += __shfl_xor_sync(0xffffffffu, l0, 2);
        l1 += __shfl_xor_sync(0xffffffffu, l1, 1);
        l1 += __shfl_xor_sync(0xffffffffu, l1, 2);

        const int sbase = (batch * 68 + slot) * 2 + group;
        float* po = g_po + (size_t)sbase * 4096;
        const int r0 = wr + g, r1 = wr + g + 8;
        #pragma unroll
        for (int nt = 0; nt < 8; nt++) {
            int cc = nt * 8 + 2 * tig;
            *(float2*)&po[r0 * 64 + cc] = make_float2(o[nt][0], o[nt][1]);
            *(float2*)&po[r1 * 64 + cc] = make_float2(o[nt][2], o[nt][3]);
        }
        if (tig == 0) {
            g_pl[sbase * 64 + r0] = l0;
            g_pl[sbase * 64 + r1] = l1;
        }
    }
}

// ---------------------------------------------------------------------------
// merge: out[tile] = sum(O partials) / sum(l partials).
// 1024 blocks x 256 threads, one float4 per thread.
// ---------------------------------------------------------------------------
__global__ __launch_bounds__(256) void merge_kernel(float* __restrict__ out)
{
    const int tile  = blockIdx.x >> 2;
    const int batch = tile >> 5;
    const int qt    = tile & 31;
    const int set   = qt >> 1;
    const int gg    = qt & 1;

    const int i4  = (blockIdx.x & 3) * 256 + threadIdx.x;
    const int row = i4 >> 4;
    const int d0  = (i4 & 15) << 2;

    float4 os = make_float4(0.f, 0.f, 0.f, 0.f);
    float ls = 0.f;
    #pragma unroll
    for (int i = 0; i < 4; i++) {
        int s = MSLOT[set][i];
        if (s >= 0) {
            int sbase = (batch * 68 + s) * 2 + gg;
            float4 v = *(const float4*)&g_po[(size_t)sbase * 4096 + row * 64 + d0];
            os.x += v.x; os.y += v.y; os.z += v.z; os.w += v.w;
            ls += g_pl[sbase * 64 + row];
        }
    }
    float inv = 1.f / ls;
    float4 w = make_float4(os.x * inv, os.y * inv, os.z * inv, os.w * inv);
    *(float4*)&out[((size_t)(batch * TT + qt * 64 + row)) * DD + d0] = w;
}

// ---------------------------------------------------------------------------
extern "C" void kernel_launch(void* const* d_in, const int* in_sizes, int n_in,
                              void* d_out, int out_size)
{
    const float* x  = (const float*)d_in[0];
    const float* Wk = (const float*)d_in[1];
    const float* Wq = (const float*)d_in[2];
    const float* Wv = (const float*)d_in[3];
    float* out = (float*)d_out;

    cudaFuncSetAttribute(proj_kernel,
                         cudaFuncAttributeMaxDynamicSharedMemorySize, PROJ_SMEM);
    cudaFuncSetAttribute(attn_kernel,
                         cudaFuncAttributeMaxDynamicSharedMemorySize, ATTN_SMEM);

    w_prep<<<128, 256>>>(Wk, Wq, Wv);
    proj_kernel<<<dim3(128, 2), 256, PROJ_SMEM>>>(x);
    attn_kernel<<<8 * 34, 256, ATTN_SMEM>>>();
    merge_kernel<<<1024, 256>>>(out);
}

// round 14
// speedup vs baseline: 1.2882x; 1.0833x over previous
#include <cuda_runtime.h>
#include <math.h>
#include <stdint.h>

#define BB 8
#define TT 2048
#define HH 1024
#define DD 64
#define NTOK (BB*TT)   // 16384

// q pre-scaled by log2(e)/8 so attn uses ex2 directly.
#define QSCALE 0.1803368801111204f

__device__ uint32_t g_qh[NTOK*32];     // Q as packed fp16x2 (pre-scaled)
__device__ uint32_t g_kh[NTOK*32];     // K as packed fp16x2
__device__ uint32_t g_vb[NTOK*32];     // V as packed fp16x2
__device__ uint32_t g_wt[32 * 6144];

// split-k partial scratch: 8 batches x 68 slots x 2 tiles x (64x64) + l
__device__ float g_po[8 * 68 * 2 * 4096];
__device__ float g_pl[8 * 68 * 2 * 64];

// ---- task tables: 34 blocks per batch, each exactly 8 k-iters, <=2 tasks.
__device__ __constant__ int T0SET[34] = {
    15,15,15,15, 14,14,14, 13,13,13, 12,12,12, 11,11,11,
    10,10, 9,9, 8,8, 7,7, 6, 5, 4, 3, 14, 10, 6, 2, 13, 5};
__device__ __constant__ int T0K0[34] = {
    0,8,16,24, 0,8,16, 0,8,16, 0,8,16, 0,8,16,
    0,8, 0,8, 0,8, 0,8, 0, 0, 0, 0, 24, 16, 8, 0, 24, 8};
__device__ __constant__ int T0K1[34] = {
    8,16,24,32, 8,16,24, 8,16,24, 8,16,24, 8,16,24,
    8,16, 8,16, 8,16, 8,16, 8, 8, 8, 8, 30, 22, 14, 6, 28, 12};
__device__ __constant__ int T1SET[34] = {
    -1,-1,-1,-1, -1,-1,-1, -1,-1,-1, -1,-1,-1, -1,-1,-1,
    -1,-1, -1,-1, -1,-1, -1,-1, -1, -1, -1, -1, 12, 8, 4, 0, 9, 1};
__device__ __constant__ int T1K0[34] = {
    0,0,0,0, 0,0,0, 0,0,0, 0,0,0, 0,0,0,
    0,0, 0,0, 0,0, 0,0, 0, 0, 0, 0, 24, 16, 8, 0, 16, 0};
__device__ __constant__ int T1K1[34] = {
    0,0,0,0, 0,0,0, 0,0,0, 0,0,0, 0,0,0,
    0,0, 0,0, 0,0, 0,0, 0, 0, 0, 0, 26, 18, 10, 2, 20, 4};

__device__ __constant__ int MSLOT[16][4] = {
    {63,-1,-1,-1}, {67,-1,-1,-1}, {62,-1,-1,-1}, {54,-1,-1,-1},
    {52,61,-1,-1}, {50,66,-1,-1}, {48,60,-1,-1}, {44,46,-1,-1},
    {40,42,59,-1}, {36,38,65,-1}, {32,34,58,-1}, {26,28,30,-1},
    {20,22,24,57}, {14,16,18,64}, {8,10,12,56},  {0,2,4,6}};

// ---------------------------------------------------------------------------
// helpers
// ---------------------------------------------------------------------------
__device__ __forceinline__ uint32_t f2tf(float f) {
    uint32_t r; asm("cvt.rna.tf32.f32 %0, %1;" : "=r"(r) : "f"(f)); return r;
}

__device__ __forceinline__ float ex2(float f) {
    float r; asm("ex2.approx.ftz.f32 %0, %1;" : "=f"(r) : "f"(f)); return r;
}

__device__ __forceinline__ uint32_t h2(float lo, float hi) {
    uint32_t r; asm("cvt.rn.f16x2.f32 %0, %1, %2;" : "=r"(r) : "f"(hi), "f"(lo));
    return r;
}

__device__ __forceinline__ void mma8(float c[4],
    uint32_t a0, uint32_t a1, uint32_t a2, uint32_t a3,
    uint32_t b0, uint32_t b1)
{
    asm volatile(
        "mma.sync.aligned.m16n8k8.row.col.f32.tf32.tf32.f32 "
        "{%0,%1,%2,%3}, {%4,%5,%6,%7}, {%8,%9}, {%0,%1,%2,%3};"
        : "+f"(c[0]), "+f"(c[1]), "+f"(c[2]), "+f"(c[3])
        : "r"(a0), "r"(a1), "r"(a2), "r"(a3), "r"(b0), "r"(b1));
}

__device__ __forceinline__ void mma16(float c[4],
    uint32_t a0, uint32_t a1, uint32_t a2, uint32_t a3,
    uint32_t b0, uint32_t b1)
{
    asm volatile(
        "mma.sync.aligned.m16n8k16.row.col.f32.f16.f16.f32 "
        "{%0,%1,%2,%3}, {%4,%5,%6,%7}, {%8,%9}, {%0,%1,%2,%3};"
        : "+f"(c[0]), "+f"(c[1]), "+f"(c[2]), "+f"(c[3])
        : "r"(a0), "r"(a1), "r"(a2), "r"(a3), "r"(b0), "r"(b1));
}

__device__ __forceinline__ void ldsm4(uint32_t& r0, uint32_t& r1,
                                      uint32_t& r2, uint32_t& r3, uint32_t addr)
{
    asm volatile("ldmatrix.sync.aligned.m8n8.x4.shared.b16 {%0,%1,%2,%3}, [%4];"
        : "=r"(r0), "=r"(r1), "=r"(r2), "=r"(r3) : "r"(addr));
}

__device__ __forceinline__ void ldsm4t(uint32_t& r0, uint32_t& r1,
                                       uint32_t& r2, uint32_t& r3, uint32_t addr)
{
    asm volatile("ldmatrix.sync.aligned.m8n8.x4.trans.shared.b16 {%0,%1,%2,%3}, [%4];"
        : "=r"(r0), "=r"(r1), "=r"(r2), "=r"(r3) : "r"(addr));
}

__device__ __forceinline__ void cpa16(uint32_t saddr, const void* g) {
    asm volatile("cp.async.cg.shared.global [%0], [%1], 16;" :: "r"(saddr), "l"(g));
}
#define CPA_COMMIT asm volatile("cp.async.commit_group;")
#define CPA_WAIT0  asm volatile("cp.async.wait_group 0;")
#define CPA_WAIT1  asm volatile("cp.async.wait_group 1;")

// ---------------------------------------------------------------------------
// w_prep: W -> tf32 in the pre-swizzled proj layout. 128 blocks x 256 thr.
// ---------------------------------------------------------------------------
__global__ __launch_bounds__(256) void w_prep(
    const float* __restrict__ Wk,
    const float* __restrict__ Wq,
    const float* __restrict__ Wv)
{
    const int t = threadIdx.x;
    const int chunk = blockIdx.x >> 2;
    const int n0 = (blockIdx.x & 3) * 48;
    const int k0 = chunk * 32;

    for (int task = t; task < 48 * 8; task += 256) {
        int n = n0 + (task >> 3), c4 = task & 7;
        const float* W = (n < 64) ? Wq : (n < 128) ? Wk : Wv;
        int ncol = n & 63;
        uint4 v;
        v.x = f2tf(W[(size_t)(k0 + c4 * 4 + 0) * DD + ncol]);
        v.y = f2tf(W[(size_t)(k0 + c4 * 4 + 1) * DD + ncol]);
        v.z = f2tf(W[(size_t)(k0 + c4 * 4 + 2) * DD + ncol]);
        v.w = f2tf(W[(size_t)(k0 + c4 * 4 + 3) * DD + ncol]);
        *(uint4*)&g_wt[chunk * 6144 + n * 32 + ((c4 ^ (n & 7)) << 2)] = v;
    }
}

// ---------------------------------------------------------------------------
// Fused projection: tf32 mma, cp.async double-buffered. Epilogue writes
// q (scaled), k, v all as packed fp16x2.
// ---------------------------------------------------------------------------
#define PROJ_SMEM 57344

__global__ __launch_bounds__(256) void proj_kernel(const float* __restrict__ x)
{
    extern __shared__ uint32_t psm[];
    const uint32_t sb = (uint32_t)__cvta_generic_to_shared(psm);

    const int t    = threadIdx.x;
    const int lane = t & 31;
    const int warp = t >> 5;
    const int g    = lane >> 2;
    const int tig  = lane & 3;
    const int warpM = warp & 3;
    const int warpN = warp >> 2;
    const int row0 = blockIdx.x * 128;
    const int nh   = blockIdx.y;

    float acc[2][6][4];
    #pragma unroll
    for (int a = 0; a < 2; a++)
        #pragma unroll
        for (int j = 0; j < 6; j++)
            #pragma unroll
            for (int e = 0; e < 4; e++) acc[a][j][e] = 0.f;

    const int arow0 = warpM * 32 + ((lane >> 3) & 1) * 8 + (lane & 7);
    const int a_kh  = (lane >> 4) & 1;
    const int brow0 = warpN * 48 + ((lane >> 4) & 1) * 8 + (lane & 7);
    const int k_kh  = (lane >> 3) & 1;

    auto load_chunk = [&](int c) {
        uint32_t xb = sb + (c & 1) * 16384;
        const float* xsrc = x + (size_t)row0 * HH + c * 32;
        #pragma unroll
        for (int i = 0; i < 4; i++) {
            int task = t + i * 256;
            int r = task >> 3, c4 = task & 7;
            cpa16(xb + r * 128 + ((c4 ^ (r & 7)) << 4),
                  xsrc + (size_t)r * HH + c4 * 4);
        }
        uint32_t wb = sb + 32768 + (c & 1) * 12288;
        const uint32_t* wsrc = g_wt + c * 6144 + nh * 3072;
        #pragma unroll
        for (int i = 0; i < 3; i++) {
            int task = t + i * 256;
            cpa16(wb + task * 16, wsrc + task * 4);
        }
    };

    load_chunk(0);
    CPA_COMMIT;

    for (int c = 0; c < 32; c++) {
        if (c + 1 < 32) {
            load_chunk(c + 1);
            CPA_COMMIT;
            CPA_WAIT1;
        } else {
            CPA_WAIT0;
        }
        __syncthreads();

        const uint32_t xb = sb + (c & 1) * 16384;
        const uint32_t wb = sb + 32768 + (c & 1) * 12288;

        #pragma unroll
        for (int ks = 0; ks < 4; ks++) {
            uint32_t a[2][4];
            #pragma unroll
            for (int mt = 0; mt < 2; mt++) {
                int ar = arow0 + mt * 16;
                ldsm4(a[mt][0], a[mt][1], a[mt][2], a[mt][3],
                      xb + ar * 128 + (((2 * ks + a_kh) ^ (ar & 7)) << 4));
            }
            #pragma unroll
            for (int p = 0; p < 3; p++) {
                int br = brow0 + p * 16;
                uint32_t b0, b1, b2, b3;
                ldsm4(b0, b1, b2, b3,
                      wb + br * 128 + (((2 * ks + k_kh) ^ (br & 7)) << 4));
                mma8(acc[0][2 * p],     a[0][0], a[0][1], a[0][2], a[0][3], b0, b1);
                mma8(acc[0][2 * p + 1], a[0][0], a[0][1], a[0][2], a[0][3], b2, b3);
                mma8(acc[1][2 * p],     a[1][0], a[1][1], a[1][2], a[1][3], b0, b1);
                mma8(acc[1][2 * p + 1], a[1][0], a[1][1], a[1][2], a[1][3], b2, b3);
            }
        }
        __syncthreads();
    }

    #pragma unroll
    for (int mt = 0; mt < 2; mt++) {
        int r = row0 + warpM * 32 + mt * 16 + g;
        #pragma unroll
        for (int j = 0; j < 6; j++) {
            int nb = nh * 96 + warpN * 48 + j * 8;
            int w = ((nb & 63) >> 1) + tig;
            uint32_t* o = (nb < 64) ? g_qh : (nb < 128) ? g_kh : g_vb;
            float sc = (nb < 64) ? QSCALE : 1.0f;
            o[(size_t)r       * 32 + w] = h2(acc[mt][j][0] * sc, acc[mt][j][1] * sc);
            o[(size_t)(r + 8) * 32 + w] = h2(acc[mt][j][2] * sc, acc[mt][j][3] * sc);
        }
    }
}

// ---------------------------------------------------------------------------
// Attention (all-fp16 tensor ops): 272 blocks x 256 threads (2 groups),
// 2 blocks/SM, 8 k-iters each. S = QK^T fp16 m16n8k16 (Q pre-scaled);
// PV fp16 with V via ldmatrix.trans. All tiles: 64 rows x 128B fp16,
// 16B chunks XOR (row&7).
// smem bytes: qs[g]@g*8192, K dbl @16384, V dbl @32768, ps[g]@49152+g*8192.
// Total 64KB -> 2 blocks/SM.
// ---------------------------------------------------------------------------
#define ATTN_SMEM 65536

// 64x128B tile, 512 chunks: per-group loader (128 threads, 4 each)
__device__ __forceinline__ void cpa_htile128(uint32_t sbase_b, const uint32_t* gsrc, int lt) {
    #pragma unroll
    for (int i = 0; i < 4; i++) {
        int task = lt + i * 128;
        int r = task >> 3, c4 = task & 7;
        cpa16(sbase_b + r * 128 + ((c4 ^ (r & 7)) << 4), gsrc + r * 32 + c4 * 4);
    }
}
// block-wide loader (256 threads, 2 each)
__device__ __forceinline__ void cpa_htile256(uint32_t sbase_b, const uint32_t* gsrc, int tid) {
    #pragma unroll
    for (int i = 0; i < 2; i++) {
        int task = tid + i * 256;
        int r = task >> 3, c4 = task & 7;
        cpa16(sbase_b + r * 128 + ((c4 ^ (r & 7)) << 4), gsrc + r * 32 + c4 * 4);
    }
}

__global__ __launch_bounds__(256, 2) void attn_kernel()
{
    extern __shared__ uint32_t sm[];
    const uint32_t base = (uint32_t)__cvta_generic_to_shared(sm);

    const int tid   = threadIdx.x;
    const int group = tid >> 7;
    const int lt    = tid & 127;
    const int lane  = tid & 31;
    const int warpg = lt >> 5;
    const int g     = lane >> 2;
    const int tig   = lane & 3;
    const int wr    = warpg * 16;
    const int batch = blockIdx.x / 34;
    const int bb    = blockIdx.x % 34;

    const uint32_t qb = base + group * 8192;

    // ldmatrix per-thread constants (A pattern: q/p rows; B pattern: k/v rows)
    const int qrow = wr + ((lane >> 3) & 1) * 8 + (lane & 7);
    const uint32_t qab = qb + qrow * 128;
    const uint32_t pab = base + 49152 + group * 8192 + qrow * 128;
    const int q_kh = (lane >> 4) & 1, q_sw = qrow & 7;
    const int krlo = ((lane >> 4) & 1) * 8 + (lane & 7);
    const int k_kh = (lane >> 3) & 1;
    // V (trans) per-lane
    const int vrlo = (lane & 7) + ((lane >> 3) & 1) * 8;     // 0..15
    const int v_nh = (lane >> 4) & 1;
    const int v_sw = vrlo & 7;

    const size_t kvoff = (size_t)batch * TT * 32;

    #pragma unroll 1
    for (int task = 0; task < 2; task++) {
        int set, k0t, k1t;
        if (task == 0) { set = T0SET[bb]; k0t = T0K0[bb]; k1t = T0K1[bb]; }
        else           { set = T1SET[bb]; k0t = T1K0[bb]; k1t = T1K1[bb];
                         if (set < 0) break; }
        const int qt   = set * 2 + group;
        const int slot = bb * 2 + task;

        __syncthreads();   // previous task's consumers done

        // prologue: own Q + shared K/V (k0t)
        cpa_htile128(qb, g_qh + kvoff + (size_t)qt * 64 * 32, lt);
        cpa_htile256(base + 16384 + (k0t & 1) * 8192,
                     g_kh + kvoff + (size_t)k0t * 64 * 32, tid);
        cpa_htile256(base + 32768 + (k0t & 1) * 8192,
                     g_vb + kvoff + (size_t)k0t * 64 * 32, tid);
        CPA_COMMIT;

        float l0 = 0.f, l1 = 0.f;
        float o[8][4];
        #pragma unroll
        for (int nt = 0; nt < 8; nt++)
            #pragma unroll
            for (int e = 0; e < 4; e++) o[nt][e] = 0.f;

        for (int kt = k0t; kt < k1t; kt++) {
            CPA_WAIT0;
            __syncthreads();   // K/V(kt), Q visible; prev iter reads done

            if (kt + 1 < k1t) {
                cpa_htile256(base + 16384 + ((kt + 1) & 1) * 8192,
                             g_kh + kvoff + (size_t)(kt + 1) * 64 * 32, tid);
                cpa_htile256(base + 32768 + ((kt + 1) & 1) * 8192,
                             g_vb + kvoff + (size_t)(kt + 1) * 64 * 32, tid);
                CPA_COMMIT;
            }

            const uint32_t kab = base + 16384 + (kt & 1) * 8192;
            const uint32_t vab = base + 32768 + (kt & 1) * 8192;

            // ---- S = Q K^T (fp16 m16n8k16; Q pre-scaled by log2e/8) ----
            float s[8][4];
            #pragma unroll
            for (int nt = 0; nt < 8; nt++)
                #pragma unroll
                for (int e = 0; e < 4; e++) s[nt][e] = 0.f;

            #pragma unroll
            for (int kb = 0; kb < 4; kb++) {
                uint32_t a0, a1, a2, a3;
                ldsm4(a0, a1, a2, a3, qab + (((2 * kb + q_kh) ^ q_sw) << 4));
                #pragma unroll
                for (int p = 0; p < 4; p++) {
                    int kr = p * 16 + krlo;
                    uint32_t b0, b1, b2, b3;
                    ldsm4(b0, b1, b2, b3,
                          kab + kr * 128 + (((2 * kb + k_kh) ^ (kr & 7)) << 4));
                    mma16(s[2 * p],     a0, a1, a2, a3, b0, b1);
                    mma16(s[2 * p + 1], a0, a1, a2, a3, b2, b3);
                }
            }

            // ---- mask (only when kt >= qt) + exp -> ps (fp16x2) ----
            const int r0 = wr + g, r1 = wr + g + 8;
            uint32_t* psw = sm + 12288 + group * 2048;
            const int sw0 = r0 & 7, sw1 = r1 & 7;
            if (kt >= qt) {
                const int gr0 = (qt << 6) + r0, gr1 = (qt << 6) + r1;
                #pragma unroll
                for (int nt = 0; nt < 8; nt++) {
                    int gc = (kt << 6) + nt * 8 + 2 * tig;
                    if (gc     > gr0) s[nt][0] = -INFINITY;
                    if (gc + 1 > gr0) s[nt][1] = -INFINITY;
                    if (gc     > gr1) s[nt][2] = -INFINITY;
                    if (gc + 1 > gr1) s[nt][3] = -INFINITY;
                }
            }
            #pragma unroll
            for (int nt = 0; nt < 8; nt++) {
                float p0 = ex2(s[nt][0]);
                float p1 = ex2(s[nt][1]);
                float p2 = ex2(s[nt][2]);
                float p3 = ex2(s[nt][3]);
                l0 += p0 + p1; l1 += p2 + p3;
                psw[r0 * 32 + ((nt ^ sw0) << 2) + tig] = h2(p0, p1);
                psw[r1 * 32 + ((nt ^ sw1) << 2) + tig] = h2(p2, p3);
            }
            __syncwarp();   // ps rows wr..wr+15 are warp-local

            // ---- O += P V (fp16; B via ldmatrix.trans on raw V) ----
            #pragma unroll
            for (int kb = 0; kb < 4; kb++) {
                uint32_t a0, a1, a2, a3;
                ldsm4(a0, a1, a2, a3, pab + (((2 * kb + q_kh) ^ q_sw) << 4));
                int vrow = kb * 16 + vrlo;
                #pragma unroll
                for (int nbp = 0; nbp < 4; nbp++) {
                    uint32_t b0, b1, b2, b3;
                    int nbx = nbp * 2 + v_nh;
                    ldsm4t(b0, b1, b2, b3,
                           vab + vrow * 128 + ((nbx ^ v_sw) << 4));
                    mma16(o[nbp * 2],     a0, a1, a2, a3, b0, b1);
                    mma16(o[nbp * 2 + 1], a0, a1, a2, a3, b2, b3);
                }
            }
        }

        // ---- epilogue: write unnormalized partials ----
        l0 += __shfl_xor_sync(0xffffffffu, l0, 1);
        l0 += __shfl_xor_sync(0xffffffffu, l0, 2);
        l1 += __shfl_xor_sync(0xffffffffu, l1, 1);
        l1 += __shfl_xor_sync(0xffffffffu, l1, 2);

        const int sbase = (batch * 68 + slot) * 2 + group;
        float* po = g_po + (size_t)sbase * 4096;
        const int r0 = wr + g, r1 = wr + g + 8;
        #pragma unroll
        for (int nt = 0; nt < 8; nt++) {
            int cc = nt * 8 + 2 * tig;
            *(float2*)&po[r0 * 64 + cc] = make_float2(o[nt][0], o[nt][1]);
            *(float2*)&po[r1 * 64 + cc] = make_float2(o[nt][2], o[nt][3]);
        }
        if (tig == 0) {
            g_pl[sbase * 64 + r0] = l0;
            g_pl[sbase * 64 + r1] = l1;
        }
    }
}

// ---------------------------------------------------------------------------
// merge: out[tile] = sum(O partials) / sum(l partials).
// 1024 blocks x 256 threads, one float4 per thread.
// ---------------------------------------------------------------------------
__global__ __launch_bounds__(256) void merge_kernel(float* __restrict__ out)
{
    const int tile  = blockIdx.x >> 2;
    const int batch = tile >> 5;
    const int qt    = tile & 31;
    const int set   = qt >> 1;
    const int gg    = qt & 1;

    const int i4  = (blockIdx.x & 3) * 256 + threadIdx.x;
    const int row = i4 >> 4;
    const int d0  = (i4 & 15) << 2;

    float4 os = make_float4(0.f, 0.f, 0.f, 0.f);
    float ls = 0.f;
    #pragma unroll
    for (int i = 0; i < 4; i++) {
        int s = MSLOT[set][i];
        if (s >= 0) {
            int sbase = (batch * 68 + s) * 2 + gg;
            float4 v = *(const float4*)&g_po[(size_t)sbase * 4096 + row * 64 + d0];
            os.x += v.x; os.y += v.y; os.z += v.z; os.w += v.w;
            ls += g_pl[sbase * 64 + row];
        }
    }
    float inv = 1.f / ls;
    float4 w = make_float4(os.x * inv, os.y * inv, os.z * inv, os.w * inv);
    *(float4*)&out[((size_t)(batch * TT + qt * 64 + row)) * DD + d0] = w;
}

// ---------------------------------------------------------------------------
extern "C" void kernel_launch(void* const* d_in, const int* in_sizes, int n_in,
                              void* d_out, int out_size)
{
    const float* x  = (const float*)d_in[0];
    const float* Wk = (const float*)d_in[1];
    const float* Wq = (const float*)d_in[2];
    const float* Wv = (const float*)d_in[3];
    float* out = (float*)d_out;

    cudaFuncSetAttribute(proj_kernel,
                         cudaFuncAttributeMaxDynamicSharedMemorySize, PROJ_SMEM);
    cudaFuncSetAttribute(attn_kernel,
                         cudaFuncAttributeMaxDynamicSharedMemorySize, ATTN_SMEM);

    w_prep<<<128, 256>>>(Wk, Wq, Wv);
    proj_kernel<<<dim3(128, 2), 256, PROJ_SMEM>>>(x);
    attn_kernel<<<8 * 34, 256, ATTN_SMEM>>>();
    merge_kernel<<<1024, 256>>>(out);
}

// round 15
// speedup vs baseline: 1.5866x; 1.2317x over previous
#include <cuda_runtime.h>
#include <math.h>
#include <stdint.h>

#define BB 8
#define TT 2048
#define HH 1024
#define DD 64
#define NTOK (BB*TT)   // 16384

// q pre-scaled by log2(e)/8 so attn uses ex2 directly.
#define QSCALE 0.1803368801111204f

__device__ uint32_t g_qh[NTOK*32];     // Q as packed fp16x2 (pre-scaled)
__device__ uint32_t g_kh[NTOK*32];     // K as packed fp16x2
__device__ uint32_t g_vb[NTOK*32];     // V as packed fp16x2
__device__ uint32_t g_wt[16 * 6144];   // W fp16, [chunk64][n][32 words], pre-swizzled

// split-k partial scratch: 8 batches x 68 slots x 2 tiles x (64x64) + l
__device__ float g_po[8 * 68 * 2 * 4096];
__device__ float g_pl[8 * 68 * 2 * 64];

// ---- task tables: 34 blocks per batch, each exactly 8 k-iters, <=2 tasks.
__device__ __constant__ int T0SET[34] = {
    15,15,15,15, 14,14,14, 13,13,13, 12,12,12, 11,11,11,
    10,10, 9,9, 8,8, 7,7, 6, 5, 4, 3, 14, 10, 6, 2, 13, 5};
__device__ __constant__ int T0K0[34] = {
    0,8,16,24, 0,8,16, 0,8,16, 0,8,16, 0,8,16,
    0,8, 0,8, 0,8, 0,8, 0, 0, 0, 0, 24, 16, 8, 0, 24, 8};
__device__ __constant__ int T0K1[34] = {
    8,16,24,32, 8,16,24, 8,16,24, 8,16,24, 8,16,24,
    8,16, 8,16, 8,16, 8,16, 8, 8, 8, 8, 30, 22, 14, 6, 28, 12};
__device__ __constant__ int T1SET[34] = {
    -1,-1,-1,-1, -1,-1,-1, -1,-1,-1, -1,-1,-1, -1,-1,-1,
    -1,-1, -1,-1, -1,-1, -1,-1, -1, -1, -1, -1, 12, 8, 4, 0, 9, 1};
__device__ __constant__ int T1K0[34] = {
    0,0,0,0, 0,0,0, 0,0,0, 0,0,0, 0,0,0,
    0,0, 0,0, 0,0, 0,0, 0, 0, 0, 0, 24, 16, 8, 0, 16, 0};
__device__ __constant__ int T1K1[34] = {
    0,0,0,0, 0,0,0, 0,0,0, 0,0,0, 0,0,0,
    0,0, 0,0, 0,0, 0,0, 0, 0, 0, 0, 26, 18, 10, 2, 20, 4};

__device__ __constant__ int MSLOT[16][4] = {
    {63,-1,-1,-1}, {67,-1,-1,-1}, {62,-1,-1,-1}, {54,-1,-1,-1},
    {52,61,-1,-1}, {50,66,-1,-1}, {48,60,-1,-1}, {44,46,-1,-1},
    {40,42,59,-1}, {36,38,65,-1}, {32,34,58,-1}, {26,28,30,-1},
    {20,22,24,57}, {14,16,18,64}, {8,10,12,56},  {0,2,4,6}};

// ---------------------------------------------------------------------------
// helpers
// ---------------------------------------------------------------------------
__device__ __forceinline__ float ex2(float f) {
    float r; asm("ex2.approx.ftz.f32 %0, %1;" : "=f"(r) : "f"(f)); return r;
}

__device__ __forceinline__ uint32_t h2(float lo, float hi) {
    uint32_t r; asm("cvt.rn.f16x2.f32 %0, %1, %2;" : "=r"(r) : "f"(hi), "f"(lo));
    return r;
}

__device__ __forceinline__ void mma16(float c[4],
    uint32_t a0, uint32_t a1, uint32_t a2, uint32_t a3,
    uint32_t b0, uint32_t b1)
{
    asm volatile(
        "mma.sync.aligned.m16n8k16.row.col.f32.f16.f16.f32 "
        "{%0,%1,%2,%3}, {%4,%5,%6,%7}, {%8,%9}, {%0,%1,%2,%3};"
        : "+f"(c[0]), "+f"(c[1]), "+f"(c[2]), "+f"(c[3])
        : "r"(a0), "r"(a1), "r"(a2), "r"(a3), "r"(b0), "r"(b1));
}

__device__ __forceinline__ void ldsm4(uint32_t& r0, uint32_t& r1,
                                      uint32_t& r2, uint32_t& r3, uint32_t addr)
{
    asm volatile("ldmatrix.sync.aligned.m8n8.x4.shared.b16 {%0,%1,%2,%3}, [%4];"
        : "=r"(r0), "=r"(r1), "=r"(r2), "=r"(r3) : "r"(addr));
}

__device__ __forceinline__ void ldsm4t(uint32_t& r0, uint32_t& r1,
                                       uint32_t& r2, uint32_t& r3, uint32_t addr)
{
    asm volatile("ldmatrix.sync.aligned.m8n8.x4.trans.shared.b16 {%0,%1,%2,%3}, [%4];"
        : "=r"(r0), "=r"(r1), "=r"(r2), "=r"(r3) : "r"(addr));
}

__device__ __forceinline__ void cpa16(uint32_t saddr, const void* g) {
    asm volatile("cp.async.cg.shared.global [%0], [%1], 16;" :: "r"(saddr), "l"(g));
}
#define CPA_COMMIT asm volatile("cp.async.commit_group;")
#define CPA_WAIT0  asm volatile("cp.async.wait_group 0;")

// ---------------------------------------------------------------------------
// w_prep: W -> fp16 in the pre-swizzled proj layout (k-chunk 64, 128B rows).
// 128 blocks x 256 threads; block b: chunk = b>>3 (0..15), n0 = (b&7)*24.
// Each task (n, c4): 8 consecutive k values for column n -> one uint4.
// ---------------------------------------------------------------------------
__global__ __launch_bounds__(256) void w_prep(
    const float* __restrict__ Wk,
    const float* __restrict__ Wq,
    const float* __restrict__ Wv)
{
    const int t = threadIdx.x;
    if (t >= 192) return;
    const int chunk = blockIdx.x >> 3;
    const int n0 = (blockIdx.x & 7) * 24;
    const int k0 = chunk * 64;

    const int n = n0 + (t >> 3), c4 = t & 7;
    const float* W = (n < 64) ? Wq : (n < 128) ? Wk : Wv;
    const int ncol = n & 63;
    float f[8];
    #pragma unroll
    for (int j = 0; j < 8; j++)
        f[j] = W[(size_t)(k0 + c4 * 8 + j) * DD + ncol];
    uint4 v;
    v.x = h2(f[0], f[1]);
    v.y = h2(f[2], f[3]);
    v.z = h2(f[4], f[5]);
    v.w = h2(f[6], f[7]);
    *(uint4*)&g_wt[chunk * 6144 + n * 32 + ((c4 ^ (n & 7)) << 2)] = v;
}

// ---------------------------------------------------------------------------
// Fused projection, all-fp16 mma16, k-chunk 64.
// Grid (128, 2): block tile M=128, N=96. 256 threads = 8 warps (4m x 2n).
// smem bytes: xs32 @0 (32K, fp32 staging), xh dbl @32768 (2x16K),
//             W dbl @65536 (2x24K). Total 114688 -> 2 blocks/SM.
// Pipeline: wait(x32,W c) -> sync -> convert x32->xh[c&1] -> sync ->
//           issue c+1 loads -> mma(xh[c&1], W[c&1]).
// ---------------------------------------------------------------------------
#define PROJ_SMEM 114688

__global__ __launch_bounds__(256, 2) void proj_kernel(const float* __restrict__ x)
{
    extern __shared__ uint32_t psm[];
    const uint32_t sb = (uint32_t)__cvta_generic_to_shared(psm);

    const int t    = threadIdx.x;
    const int lane = t & 31;
    const int warp = t >> 5;
    const int g    = lane >> 2;
    const int tig  = lane & 3;
    const int warpM = warp & 3;    // 0..3
    const int warpN = warp >> 2;   // 0..1
    const int row0 = blockIdx.x * 128;
    const int nh   = blockIdx.y;

    float acc[2][6][4];
    #pragma unroll
    for (int a = 0; a < 2; a++)
        #pragma unroll
        for (int j = 0; j < 6; j++)
            #pragma unroll
            for (int e = 0; e < 4; e++) acc[a][j][e] = 0.f;

    const int arow0 = warpM * 32 + ((lane >> 3) & 1) * 8 + (lane & 7);
    const int a_kh  = (lane >> 4) & 1;
    const int brow0 = warpN * 48 + ((lane >> 4) & 1) * 8 + (lane & 7);
    const int k_kh  = (lane >> 3) & 1;

    auto load_x = [&](int c) {
        const float* xsrc = x + (size_t)row0 * HH + c * 64;
        #pragma unroll
        for (int i = 0; i < 8; i++) {
            int task = t + i * 256;
            int r = task >> 4, c4 = task & 15;
            cpa16(sb + r * 256 + c4 * 16, xsrc + (size_t)r * HH + c4 * 4);
        }
    };
    auto load_w = [&](int c) {
        uint32_t wb = sb + 65536 + (c & 1) * 24576;
        const uint32_t* wsrc = g_wt + c * 6144 + nh * 3072;
        #pragma unroll
        for (int i = 0; i < 6; i++) {
            int task = t + i * 256;
            cpa16(wb + task * 16, wsrc + task * 4);
        }
    };

    load_x(0);
    load_w(0);
    CPA_COMMIT;

    for (int c = 0; c < 16; c++) {
        CPA_WAIT0;
        __syncthreads();   // xs32(c), W(c) visible; prev iter's xh reads done

        // convert xs32 (fp32) -> xh[c&1] (fp16, 128B rows, chunk XOR (r&7))
        uint32_t* xh = psm + (32768 + (c & 1) * 16384) / 4;
        #pragma unroll
        for (int i = 0; i < 8; i++) {
            int task = t + i * 256;
            int r = task >> 4, c4 = task & 15;
            float4 v = *(const float4*)&psm[r * 64 + c4 * 4];
            uint32_t w0 = h2(v.x, v.y), w1 = h2(v.z, v.w);
            int idx = r * 32 + (((c4 >> 1) ^ (r & 7)) << 2) + (c4 & 1) * 2;
            *(uint2*)&xh[idx] = make_uint2(w0, w1);
        }
        __syncthreads();   // xh visible; xs32 free for next chunk

        if (c + 1 < 16) {
            load_x(c + 1);
            load_w(c + 1);
            CPA_COMMIT;
        }

        const uint32_t xb = sb + 32768 + (c & 1) * 16384;
        const uint32_t wb = sb + 65536 + (c & 1) * 24576;

        #pragma unroll
        for (int kb = 0; kb < 4; kb++) {
            uint32_t a[2][4];
            #pragma unroll
            for (int mt = 0; mt < 2; mt++) {
                int ar = arow0 + mt * 16;
                ldsm4(a[mt][0], a[mt][1], a[mt][2], a[mt][3],
                      xb + ar * 128 + (((2 * kb + a_kh) ^ (ar & 7)) << 4));
            }
            #pragma unroll
            for (int p = 0; p < 3; p++) {
                int br = brow0 + p * 16;
                uint32_t b0, b1, b2, b3;
                ldsm4(b0, b1, b2, b3,
                      wb + br * 128 + (((2 * kb + k_kh) ^ (br & 7)) << 4));
                mma16(acc[0][2 * p],     a[0][0], a[0][1], a[0][2], a[0][3], b0, b1);
                mma16(acc[0][2 * p + 1], a[0][0], a[0][1], a[0][2], a[0][3], b2, b3);
                mma16(acc[1][2 * p],     a[1][0], a[1][1], a[1][2], a[1][3], b0, b1);
                mma16(acc[1][2 * p + 1], a[1][0], a[1][1], a[1][2], a[1][3], b2, b3);
            }
        }
    }

    #pragma unroll
    for (int mt = 0; mt < 2; mt++) {
        int r = row0 + warpM * 32 + mt * 16 + g;
        #pragma unroll
        for (int j = 0; j < 6; j++) {
            int nb = nh * 96 + warpN * 48 + j * 8;
            int w = ((nb & 63) >> 1) + tig;
            uint32_t* o = (nb < 64) ? g_qh : (nb < 128) ? g_kh : g_vb;
            float sc = (nb < 64) ? QSCALE : 1.0f;
            o[(size_t)r       * 32 + w] = h2(acc[mt][j][0] * sc, acc[mt][j][1] * sc);
            o[(size_t)(r + 8) * 32 + w] = h2(acc[mt][j][2] * sc, acc[mt][j][3] * sc);
        }
    }
}

// ---------------------------------------------------------------------------
// Attention (all-fp16, unchanged from R14 best): 272 blocks x 256 threads
// (2 groups), 2 blocks/SM, 8 k-iters each.
// smem bytes: qs[g]@g*8192, K dbl @16384, V dbl @32768, ps[g]@49152+g*8192.
// ---------------------------------------------------------------------------
#define ATTN_SMEM 65536

__device__ __forceinline__ void cpa_htile128(uint32_t sbase_b, const uint32_t* gsrc, int lt) {
    #pragma unroll
    for (int i = 0; i < 4; i++) {
        int task = lt + i * 128;
        int r = task >> 3, c4 = task & 7;
        cpa16(sbase_b + r * 128 + ((c4 ^ (r & 7)) << 4), gsrc + r * 32 + c4 * 4);
    }
}
__device__ __forceinline__ void cpa_htile256(uint32_t sbase_b, const uint32_t* gsrc, int tid) {
    #pragma unroll
    for (int i = 0; i < 2; i++) {
        int task = tid + i * 256;
        int r = task >> 3, c4 = task & 7;
        cpa16(sbase_b + r * 128 + ((c4 ^ (r & 7)) << 4), gsrc + r * 32 + c4 * 4);
    }
}

__global__ __launch_bounds__(256, 2) void attn_kernel()
{
    extern __shared__ uint32_t sm[];
    const uint32_t base = (uint32_t)__cvta_generic_to_shared(sm);

    const int tid   = threadIdx.x;
    const int group = tid >> 7;
    const int lt    = tid & 127;
    const int lane  = tid & 31;
    const int warpg = lt >> 5;
    const int g     = lane >> 2;
    const int tig   = lane & 3;
    const int wr    = warpg * 16;
    const int batch = blockIdx.x / 34;
    const int bb    = blockIdx.x % 34;

    const uint32_t qb = base + group * 8192;

    const int qrow = wr + ((lane >> 3) & 1) * 8 + (lane & 7);
    const uint32_t qab = qb + qrow * 128;
    const uint32_t pab = base + 49152 + group * 8192 + qrow * 128;
    const int q_kh = (lane >> 4) & 1, q_sw = qrow & 7;
    const int krlo = ((lane >> 4) & 1) * 8 + (lane & 7);
    const int k_kh = (lane >> 3) & 1;
    const int vrlo = (lane & 7) + ((lane >> 3) & 1) * 8;
    const int v_nh = (lane >> 4) & 1;
    const int v_sw = vrlo & 7;

    const size_t kvoff = (size_t)batch * TT * 32;

    #pragma unroll 1
    for (int task = 0; task < 2; task++) {
        int set, k0t, k1t;
        if (task == 0) { set = T0SET[bb]; k0t = T0K0[bb]; k1t = T0K1[bb]; }
        else           { set = T1SET[bb]; k0t = T1K0[bb]; k1t = T1K1[bb];
                         if (set < 0) break; }
        const int qt   = set * 2 + group;
        const int slot = bb * 2 + task;

        __syncthreads();

        cpa_htile128(qb, g_qh + kvoff + (size_t)qt * 64 * 32, lt);
        cpa_htile256(base + 16384 + (k0t & 1) * 8192,
                     g_kh + kvoff + (size_t)k0t * 64 * 32, tid);
        cpa_htile256(base + 32768 + (k0t & 1) * 8192,
                     g_vb + kvoff + (size_t)k0t * 64 * 32, tid);
        CPA_COMMIT;

        float l0 = 0.f, l1 = 0.f;
        float o[8][4];
        #pragma unroll
        for (int nt = 0; nt < 8; nt++)
            #pragma unroll
            for (int e = 0; e < 4; e++) o[nt][e] = 0.f;

        for (int kt = k0t; kt < k1t; kt++) {
            CPA_WAIT0;
            __syncthreads();

            if (kt + 1 < k1t) {
                cpa_htile256(base + 16384 + ((kt + 1) & 1) * 8192,
                             g_kh + kvoff + (size_t)(kt + 1) * 64 * 32, tid);
                cpa_htile256(base + 32768 + ((kt + 1) & 1) * 8192,
                             g_vb + kvoff + (size_t)(kt + 1) * 64 * 32, tid);
                CPA_COMMIT;
            }

            const uint32_t kab = base + 16384 + (kt & 1) * 8192;
            const uint32_t vab = base + 32768 + (kt & 1) * 8192;

            float s[8][4];
            #pragma unroll
            for (int nt = 0; nt < 8; nt++)
                #pragma unroll
                for (int e = 0; e < 4; e++) s[nt][e] = 0.f;

            #pragma unroll
            for (int kb = 0; kb < 4; kb++) {
                uint32_t a0, a1, a2, a3;
                ldsm4(a0, a1, a2, a3, qab + (((2 * kb + q_kh) ^ q_sw) << 4));
                #pragma unroll
                for (int p = 0; p < 4; p++) {
                    int kr = p * 16 + krlo;
                    uint32_t b0, b1, b2, b3;
                    ldsm4(b0, b1, b2, b3,
                          kab + kr * 128 + (((2 * kb + k_kh) ^ (kr & 7)) << 4));
                    mma16(s[2 * p],     a0, a1, a2, a3, b0, b1);
                    mma16(s[2 * p + 1], a0, a1, a2, a3, b2, b3);
                }
            }

            const int r0 = wr + g, r1 = wr + g + 8;
            uint32_t* psw = sm + 12288 + group * 2048;
            const int sw0 = r0 & 7, sw1 = r1 & 7;
            if (kt >= qt) {
                const int gr0 = (qt << 6) + r0, gr1 = (qt << 6) + r1;
                #pragma unroll
                for (int nt = 0; nt < 8; nt++) {
                    int gc = (kt << 6) + nt * 8 + 2 * tig;
                    if (gc     > gr0) s[nt][0] = -INFINITY;
                    if (gc + 1 > gr0) s[nt][1] = -INFINITY;
                    if (gc     > gr1) s[nt][2] = -INFINITY;
                    if (gc + 1 > gr1) s[nt][3] = -INFINITY;
                }
            }
            #pragma unroll
            for (int nt = 0; nt < 8; nt++) {
                float p0 = ex2(s[nt][0]);
                float p1 = ex2(s[nt][1]);
                float p2 = ex2(s[nt][2]);
                float p3 = ex2(s[nt][3]);
                l0 += p0 + p1; l1 += p2 + p3;
                psw[r0 * 32 + ((nt ^ sw0) << 2) + tig] = h2(p0, p1);
                psw[r1 * 32 + ((nt ^ sw1) << 2) + tig] = h2(p2, p3);
            }
            __syncwarp();

            #pragma unroll
            for (int kb = 0; kb < 4; kb++) {
                uint32_t a0, a1, a2, a3;
                ldsm4(a0, a1, a2, a3, pab + (((2 * kb + q_kh) ^ q_sw) << 4));
                int vrow = kb * 16 + vrlo;
                #pragma unroll
                for (int nbp = 0; nbp < 4; nbp++) {
                    uint32_t b0, b1, b2, b3;
                    int nbx = nbp * 2 + v_nh;
                    ldsm4t(b0, b1, b2, b3,
                           vab + vrow * 128 + ((nbx ^ v_sw) << 4));
                    mma16(o[nbp * 2],     a0, a1, a2, a3, b0, b1);
                    mma16(o[nbp * 2 + 1], a0, a1, a2, a3, b2, b3);
                }
            }
        }

        l0 += __shfl_xor_sync(0xffffffffu, l0, 1);
        l0 += __shfl_xor_sync(0xffffffffu, l0, 2);
        l1 += __shfl_xor_sync(0xffffffffu, l1, 1);
        l1 += __shfl_xor_sync(0xffffffffu, l1, 2);

        const int sbase = (batch * 68 + slot) * 2 + group;
        float* po = g_po + (size_t)sbase * 4096;
        const int r0 = wr + g, r1 = wr + g + 8;
        #pragma unroll
        for (int nt = 0; nt < 8; nt++) {
            int cc = nt * 8 + 2 * tig;
            *(float2*)&po[r0 * 64 + cc] = make_float2(o[nt][0], o[nt][1]);
            *(float2*)&po[r1 * 64 + cc] = make_float2(o[nt][2], o[nt][3]);
        }
        if (tig == 0) {
            g_pl[sbase * 64 + r0] = l0;
            g_pl[sbase * 64 + r1] = l1;
        }
    }
}

// ---------------------------------------------------------------------------
// merge: out[tile] = sum(O partials) / sum(l partials).
// ---------------------------------------------------------------------------
__global__ __launch_bounds__(256) void merge_kernel(float* __restrict__ out)
{
    const int tile  = blockIdx.x >> 2;
    const int batch = tile >> 5;
    const int qt    = tile & 31;
    const int set   = qt >> 1;
    const int gg    = qt & 1;

    const int i4  = (blockIdx.x & 3) * 256 + threadIdx.x;
    const int row = i4 >> 4;
    const int d0  = (i4 & 15) << 2;

    float4 os = make_float4(0.f, 0.f, 0.f, 0.f);
    float ls = 0.f;
    #pragma unroll
    for (int i = 0; i < 4; i++) {
        int s = MSLOT[set][i];
        if (s >= 0) {
            int sbase = (batch * 68 + s) * 2 + gg;
            float4 v = *(const float4*)&g_po[(size_t)sbase * 4096 + row * 64 + d0];
            os.x += v.x; os.y += v.y; os.z += v.z; os.w += v.w;
            ls += g_pl[sbase * 64 + row];
        }
    }
    float inv = 1.f / ls;
    float4 w = make_float4(os.x * inv, os.y * inv, os.z * inv, os.w * inv);
    *(float4*)&out[((size_t)(batch * TT + qt * 64 + row)) * DD + d0] = w;
}

// ---------------------------------------------------------------------------
extern "C" void kernel_launch(void* const* d_in, const int* in_sizes, int n_in,
                              void* d_out, int out_size)
{
    const float* x  = (const float*)d_in[0];
    const float* Wk = (const float*)d_in[1];
    const float* Wq = (const float*)d_in[2];
    const float* Wv = (const float*)d_in[3];
    float* out = (float*)d_out;

    cudaFuncSetAttribute(proj_kernel,
                         cudaFuncAttributeMaxDynamicSharedMemorySize, PROJ_SMEM);
    cudaFuncSetAttribute(attn_kernel,
                         cudaFuncAttributeMaxDynamicSharedMemorySize, ATTN_SMEM);

    w_prep<<<128, 256>>>(Wk, Wq, Wv);
    proj_kernel<<<dim3(128, 2), 256, PROJ_SMEM>>>(x);
    attn_kernel<<<8 * 34, 256, ATTN_SMEM>>>();
    merge_kernel<<<1024, 256>>>(out);
}

// round 16
// speedup vs baseline: 1.5994x; 1.0081x over previous
#include <cuda_runtime.h>
#include <math.h>
#include <stdint.h>

#define BB 8
#define TT 2048
#define HH 1024
#define DD 64
#define NTOK (BB*TT)   // 16384

// q pre-scaled by log2(e)/8 so attn uses ex2 directly.
#define QSCALE 0.1803368801111204f

__device__ uint32_t g_qh[NTOK*32];     // Q as packed fp16x2 (pre-scaled)
__device__ uint32_t g_kh[NTOK*32];     // K as packed fp16x2
__device__ uint32_t g_vb[NTOK*32];     // V as packed fp16x2
__device__ uint32_t g_wt[16 * 6144];   // W fp16, [chunk64][n][32 words], pre-swizzled

// split-k partial scratch: 8 batches x 68 slots x 2 tiles x (64x64) + l
__device__ float g_po[8 * 68 * 2 * 4096];
__device__ float g_pl[8 * 68 * 2 * 64];

// ---- task tables: 34 blocks per batch, each exactly 8 k-iters, <=2 tasks.
__device__ __constant__ int T0SET[34] = {
    15,15,15,15, 14,14,14, 13,13,13, 12,12,12, 11,11,11,
    10,10, 9,9, 8,8, 7,7, 6, 5, 4, 3, 14, 10, 6, 2, 13, 5};
__device__ __constant__ int T0K0[34] = {
    0,8,16,24, 0,8,16, 0,8,16, 0,8,16, 0,8,16,
    0,8, 0,8, 0,8, 0,8, 0, 0, 0, 0, 24, 16, 8, 0, 24, 8};
__device__ __constant__ int T0K1[34] = {
    8,16,24,32, 8,16,24, 8,16,24, 8,16,24, 8,16,24,
    8,16, 8,16, 8,16, 8,16, 8, 8, 8, 8, 30, 22, 14, 6, 28, 12};
__device__ __constant__ int T1SET[34] = {
    -1,-1,-1,-1, -1,-1,-1, -1,-1,-1, -1,-1,-1, -1,-1,-1,
    -1,-1, -1,-1, -1,-1, -1,-1, -1, -1, -1, -1, 12, 8, 4, 0, 9, 1};
__device__ __constant__ int T1K0[34] = {
    0,0,0,0, 0,0,0, 0,0,0, 0,0,0, 0,0,0,
    0,0, 0,0, 0,0, 0,0, 0, 0, 0, 0, 24, 16, 8, 0, 16, 0};
__device__ __constant__ int T1K1[34] = {
    0,0,0,0, 0,0,0, 0,0,0, 0,0,0, 0,0,0,
    0,0, 0,0, 0,0, 0,0, 0, 0, 0, 0, 26, 18, 10, 2, 20, 4};

__device__ __constant__ int MSLOT[16][4] = {
    {63,-1,-1,-1}, {67,-1,-1,-1}, {62,-1,-1,-1}, {54,-1,-1,-1},
    {52,61,-1,-1}, {50,66,-1,-1}, {48,60,-1,-1}, {44,46,-1,-1},
    {40,42,59,-1}, {36,38,65,-1}, {32,34,58,-1}, {26,28,30,-1},
    {20,22,24,57}, {14,16,18,64}, {8,10,12,56},  {0,2,4,6}};

// ---------------------------------------------------------------------------
// helpers
// ---------------------------------------------------------------------------
__device__ __forceinline__ float ex2(float f) {
    float r; asm("ex2.approx.ftz.f32 %0, %1;" : "=f"(r) : "f"(f)); return r;
}

__device__ __forceinline__ uint32_t h2(float lo, float hi) {
    uint32_t r; asm("cvt.rn.f16x2.f32 %0, %1, %2;" : "=r"(r) : "f"(hi), "f"(lo));
    return r;
}

__device__ __forceinline__ void mma16(float c[4],
    uint32_t a0, uint32_t a1, uint32_t a2, uint32_t a3,
    uint32_t b0, uint32_t b1)
{
    asm volatile(
        "mma.sync.aligned.m16n8k16.row.col.f32.f16.f16.f32 "
        "{%0,%1,%2,%3}, {%4,%5,%6,%7}, {%8,%9}, {%0,%1,%2,%3};"
        : "+f"(c[0]), "+f"(c[1]), "+f"(c[2]), "+f"(c[3])
        : "r"(a0), "r"(a1), "r"(a2), "r"(a3), "r"(b0), "r"(b1));
}

__device__ __forceinline__ void ldsm4(uint32_t& r0, uint32_t& r1,
                                      uint32_t& r2, uint32_t& r3, uint32_t addr)
{
    asm volatile("ldmatrix.sync.aligned.m8n8.x4.shared.b16 {%0,%1,%2,%3}, [%4];"
        : "=r"(r0), "=r"(r1), "=r"(r2), "=r"(r3) : "r"(addr));
}

__device__ __forceinline__ void ldsm4t(uint32_t& r0, uint32_t& r1,
                                       uint32_t& r2, uint32_t& r3, uint32_t addr)
{
    asm volatile("ldmatrix.sync.aligned.m8n8.x4.trans.shared.b16 {%0,%1,%2,%3}, [%4];"
        : "=r"(r0), "=r"(r1), "=r"(r2), "=r"(r3) : "r"(addr));
}

__device__ __forceinline__ void cpa16(uint32_t saddr, const void* g) {
    asm volatile("cp.async.cg.shared.global [%0], [%1], 16;" :: "r"(saddr), "l"(g));
}
#define CPA_COMMIT asm volatile("cp.async.commit_group;")
#define CPA_WAIT0  asm volatile("cp.async.wait_group 0;")

// ---------------------------------------------------------------------------
// w_prep: W -> fp16 pre-swizzled (k-chunk 64, 128B rows). Coalesced version:
// 48 blocks (16 chunks x 3 matrices) x 256 threads, staged via smem.
// ---------------------------------------------------------------------------
#define WPREP_SMEM 69632   // 64 cols x 68-float rows (transposed staging)

__global__ __launch_bounds__(256) void w_prep(
    const float* __restrict__ Wk,
    const float* __restrict__ Wq,
    const float* __restrict__ Wv)
{
    extern __shared__ float sW[];   // sW[col][68] holds W[k][col] transposed
    const int t = threadIdx.x;
    const int chunk = blockIdx.x / 3;
    const int m = blockIdx.x % 3;
    const float* W = (m == 0) ? Wq : (m == 1) ? Wk : Wv;
    const int k0 = chunk * 64;
    const int nbase = m * 64;

    // coalesced load of W[k0..k0+63][0..63], transposed into sW
    #pragma unroll
    for (int i = 0; i < 4; i++) {
        int idx = t + i * 256;
        int r = idx >> 4, c4 = idx & 15;
        float4 v = *(const float4*)&W[(size_t)(k0 + r) * DD + c4 * 4];
        sW[(c4 * 4 + 0) * 68 + r] = v.x;
        sW[(c4 * 4 + 1) * 68 + r] = v.y;
        sW[(c4 * 4 + 2) * 68 + r] = v.z;
        sW[(c4 * 4 + 3) * 68 + r] = v.w;
    }
    __syncthreads();

    #pragma unroll
    for (int i = 0; i < 2; i++) {
        int task = t + i * 256;          // 512 tasks: (ncol, c4)
        int ncol = task >> 3, c4 = task & 7;
        const float* src = &sW[ncol * 68 + c4 * 8];
        float4 lo = *(const float4*)src;
        float4 hi = *(const float4*)(src + 4);
        uint4 v;
        v.x = h2(lo.x, lo.y);
        v.y = h2(lo.z, lo.w);
        v.z = h2(hi.x, hi.y);
        v.w = h2(hi.z, hi.w);
        int n = nbase + ncol;
        *(uint4*)&g_wt[chunk * 6144 + n * 32 + ((c4 ^ (n & 7)) << 2)] = v;
    }
}

// ---------------------------------------------------------------------------
// Fused projection, all-fp16 mma16, k-chunk 64 (unchanged from R15 best).
// ---------------------------------------------------------------------------
#define PROJ_SMEM 114688

__global__ __launch_bounds__(256, 2) void proj_kernel(const float* __restrict__ x)
{
    extern __shared__ uint32_t psm[];
    const uint32_t sb = (uint32_t)__cvta_generic_to_shared(psm);

    const int t    = threadIdx.x;
    const int lane = t & 31;
    const int warp = t >> 5;
    const int g    = lane >> 2;
    const int tig  = lane & 3;
    const int warpM = warp & 3;
    const int warpN = warp >> 2;
    const int row0 = blockIdx.x * 128;
    const int nh   = blockIdx.y;

    float acc[2][6][4];
    #pragma unroll
    for (int a = 0; a < 2; a++)
        #pragma unroll
        for (int j = 0; j < 6; j++)
            #pragma unroll
            for (int e = 0; e < 4; e++) acc[a][j][e] = 0.f;

    const int arow0 = warpM * 32 + ((lane >> 3) & 1) * 8 + (lane & 7);
    const int a_kh  = (lane >> 4) & 1;
    const int brow0 = warpN * 48 + ((lane >> 4) & 1) * 8 + (lane & 7);
    const int k_kh  = (lane >> 3) & 1;

    auto load_x = [&](int c) {
        const float* xsrc = x + (size_t)row0 * HH + c * 64;
        #pragma unroll
        for (int i = 0; i < 8; i++) {
            int task = t + i * 256;
            int r = task >> 4, c4 = task & 15;
            cpa16(sb + r * 256 + c4 * 16, xsrc + (size_t)r * HH + c4 * 4);
        }
    };
    auto load_w = [&](int c) {
        uint32_t wb = sb + 65536 + (c & 1) * 24576;
        const uint32_t* wsrc = g_wt + c * 6144 + nh * 3072;
        #pragma unroll
        for (int i = 0; i < 6; i++) {
            int task = t + i * 256;
            cpa16(wb + task * 16, wsrc + task * 4);
        }
    };

    load_x(0);
    load_w(0);
    CPA_COMMIT;

    for (int c = 0; c < 16; c++) {
        CPA_WAIT0;
        __syncthreads();

        uint32_t* xh = psm + (32768 + (c & 1) * 16384) / 4;
        #pragma unroll
        for (int i = 0; i < 8; i++) {
            int task = t + i * 256;
            int r = task >> 4, c4 = task & 15;
            float4 v = *(const float4*)&psm[r * 64 + c4 * 4];
            uint32_t w0 = h2(v.x, v.y), w1 = h2(v.z, v.w);
            int idx = r * 32 + (((c4 >> 1) ^ (r & 7)) << 2) + (c4 & 1) * 2;
            *(uint2*)&xh[idx] = make_uint2(w0, w1);
        }
        __syncthreads();

        if (c + 1 < 16) {
            load_x(c + 1);
            load_w(c + 1);
            CPA_COMMIT;
        }

        const uint32_t xb = sb + 32768 + (c & 1) * 16384;
        const uint32_t wb = sb + 65536 + (c & 1) * 24576;

        #pragma unroll
        for (int kb = 0; kb < 4; kb++) {
            uint32_t a[2][4];
            #pragma unroll
            for (int mt = 0; mt < 2; mt++) {
                int ar = arow0 + mt * 16;
                ldsm4(a[mt][0], a[mt][1], a[mt][2], a[mt][3],
                      xb + ar * 128 + (((2 * kb + a_kh) ^ (ar & 7)) << 4));
            }
            #pragma unroll
            for (int p = 0; p < 3; p++) {
                int br = brow0 + p * 16;
                uint32_t b0, b1, b2, b3;
                ldsm4(b0, b1, b2, b3,
                      wb + br * 128 + (((2 * kb + k_kh) ^ (br & 7)) << 4));
                mma16(acc[0][2 * p],     a[0][0], a[0][1], a[0][2], a[0][3], b0, b1);
                mma16(acc[0][2 * p + 1], a[0][0], a[0][1], a[0][2], a[0][3], b2, b3);
                mma16(acc[1][2 * p],     a[1][0], a[1][1], a[1][2], a[1][3], b0, b1);
                mma16(acc[1][2 * p + 1], a[1][0], a[1][1], a[1][2], a[1][3], b2, b3);
            }
        }
    }

    #pragma unroll
    for (int mt = 0; mt < 2; mt++) {
        int r = row0 + warpM * 32 + mt * 16 + g;
        #pragma unroll
        for (int j = 0; j < 6; j++) {
            int nb = nh * 96 + warpN * 48 + j * 8;
            int w = ((nb & 63) >> 1) + tig;
            uint32_t* o = (nb < 64) ? g_qh : (nb < 128) ? g_kh : g_vb;
            float sc = (nb < 64) ? QSCALE : 1.0f;
            o[(size_t)r       * 32 + w] = h2(acc[mt][j][0] * sc, acc[mt][j][1] * sc);
            o[(size_t)(r + 8) * 32 + w] = h2(acc[mt][j][2] * sc, acc[mt][j][3] * sc);
        }
    }
}

// ---------------------------------------------------------------------------
// Attention (all-fp16): 272 blocks x 256 threads (2 groups), 2 blocks/SM,
// 8 k-iters each. PV A-fragments come DIRECTLY from the exp'd S registers
// (mma C layout == mma A layout) — no P smem, no syncwarp, no extra LDSM.
// smem bytes: qs[g]@g*8192, K dbl @16384, V dbl @32768. Total 48KB.
// ---------------------------------------------------------------------------
#define ATTN_SMEM 49152

__device__ __forceinline__ void cpa_htile128(uint32_t sbase_b, const uint32_t* gsrc, int lt) {
    #pragma unroll
    for (int i = 0; i < 4; i++) {
        int task = lt + i * 128;
        int r = task >> 3, c4 = task & 7;
        cpa16(sbase_b + r * 128 + ((c4 ^ (r & 7)) << 4), gsrc + r * 32 + c4 * 4);
    }
}
__device__ __forceinline__ void cpa_htile256(uint32_t sbase_b, const uint32_t* gsrc, int tid) {
    #pragma unroll
    for (int i = 0; i < 2; i++) {
        int task = tid + i * 256;
        int r = task >> 3, c4 = task & 7;
        cpa16(sbase_b + r * 128 + ((c4 ^ (r & 7)) << 4), gsrc + r * 32 + c4 * 4);
    }
}

__global__ __launch_bounds__(256, 2) void attn_kernel()
{
    extern __shared__ uint32_t sm[];
    const uint32_t base = (uint32_t)__cvta_generic_to_shared(sm);

    const int tid   = threadIdx.x;
    const int group = tid >> 7;
    const int lt    = tid & 127;
    const int lane  = tid & 31;
    const int warpg = lt >> 5;
    const int g     = lane >> 2;
    const int tig   = lane & 3;
    const int wr    = warpg * 16;
    const int batch = blockIdx.x / 34;
    const int bb    = blockIdx.x % 34;

    const uint32_t qb = base + group * 8192;

    const int qrow = wr + ((lane >> 3) & 1) * 8 + (lane & 7);
    const uint32_t qab = qb + qrow * 128;
    const int q_kh = (lane >> 4) & 1, q_sw = qrow & 7;
    const int krlo = ((lane >> 4) & 1) * 8 + (lane & 7);
    const int k_kh = (lane >> 3) & 1;
    const int vrlo = (lane & 7) + ((lane >> 3) & 1) * 8;
    const int v_nh = (lane >> 4) & 1;
    const int v_sw = vrlo & 7;

    const size_t kvoff = (size_t)batch * TT * 32;

    #pragma unroll 1
    for (int task = 0; task < 2; task++) {
        int set, k0t, k1t;
        if (task == 0) { set = T0SET[bb]; k0t = T0K0[bb]; k1t = T0K1[bb]; }
        else           { set = T1SET[bb]; k0t = T1K0[bb]; k1t = T1K1[bb];
                         if (set < 0) break; }
        const int qt   = set * 2 + group;
        const int slot = bb * 2 + task;

        __syncthreads();   // previous task's consumers done

        cpa_htile128(qb, g_qh + kvoff + (size_t)qt * 64 * 32, lt);
        cpa_htile256(base + 16384 + (k0t & 1) * 8192,
                     g_kh + kvoff + (size_t)k0t * 64 * 32, tid);
        cpa_htile256(base + 32768 + (k0t & 1) * 8192,
                     g_vb + kvoff + (size_t)k0t * 64 * 32, tid);
        CPA_COMMIT;

        float l0 = 0.f, l1 = 0.f;
        float o[8][4];
        #pragma unroll
        for (int nt = 0; nt < 8; nt++)
            #pragma unroll
            for (int e = 0; e < 4; e++) o[nt][e] = 0.f;

        for (int kt = k0t; kt < k1t; kt++) {
            CPA_WAIT0;
            __syncthreads();   // K/V(kt), Q visible; prev iter reads done

            if (kt + 1 < k1t) {
                cpa_htile256(base + 16384 + ((kt + 1) & 1) * 8192,
                             g_kh + kvoff + (size_t)(kt + 1) * 64 * 32, tid);
                cpa_htile256(base + 32768 + ((kt + 1) & 1) * 8192,
                             g_vb + kvoff + (size_t)(kt + 1) * 64 * 32, tid);
                CPA_COMMIT;
            }

            const uint32_t kab = base + 16384 + (kt & 1) * 8192;
            const uint32_t vab = base + 32768 + (kt & 1) * 8192;

            // ---- S = Q K^T (fp16 m16n8k16; Q pre-scaled by log2e/8) ----
            float s[8][4];
            #pragma unroll
            for (int nt = 0; nt < 8; nt++)
                #pragma unroll
                for (int e = 0; e < 4; e++) s[nt][e] = 0.f;

            #pragma unroll
            for (int kb = 0; kb < 4; kb++) {
                uint32_t a0, a1, a2, a3;
                ldsm4(a0, a1, a2, a3, qab + (((2 * kb + q_kh) ^ q_sw) << 4));
                #pragma unroll
                for (int p = 0; p < 4; p++) {
                    int kr = p * 16 + krlo;
                    uint32_t b0, b1, b2, b3;
                    ldsm4(b0, b1, b2, b3,
                          kab + kr * 128 + (((2 * kb + k_kh) ^ (kr & 7)) << 4));
                    mma16(s[2 * p],     a0, a1, a2, a3, b0, b1);
                    mma16(s[2 * p + 1], a0, a1, a2, a3, b2, b3);
                }
            }

            // ---- mask (only when kt >= qt) + exp in place ----
            const int r0 = wr + g, r1 = wr + g + 8;
            if (kt >= qt) {
                const int gr0 = (qt << 6) + r0, gr1 = (qt << 6) + r1;
                #pragma unroll
                for (int nt = 0; nt < 8; nt++) {
                    int gc = (kt << 6) + nt * 8 + 2 * tig;
                    if (gc     > gr0) s[nt][0] = -INFINITY;
                    if (gc + 1 > gr0) s[nt][1] = -INFINITY;
                    if (gc     > gr1) s[nt][2] = -INFINITY;
                    if (gc + 1 > gr1) s[nt][3] = -INFINITY;
                }
            }
            #pragma unroll
            for (int nt = 0; nt < 8; nt++) {
                s[nt][0] = ex2(s[nt][0]);
                s[nt][1] = ex2(s[nt][1]);
                s[nt][2] = ex2(s[nt][2]);
                s[nt][3] = ex2(s[nt][3]);
                l0 += s[nt][0] + s[nt][1];
                l1 += s[nt][2] + s[nt][3];
            }

            // ---- O += P V: A fragments straight from registers ----
            #pragma unroll
            for (int kb = 0; kb < 4; kb++) {
                uint32_t a0 = h2(s[2 * kb][0],     s[2 * kb][1]);
                uint32_t a1 = h2(s[2 * kb][2],     s[2 * kb][3]);
                uint32_t a2 = h2(s[2 * kb + 1][0], s[2 * kb + 1][1]);
                uint32_t a3 = h2(s[2 * kb + 1][2], s[2 * kb + 1][3]);
                int vrow = kb * 16 + vrlo;
                #pragma unroll
                for (int nbp = 0; nbp < 4; nbp++) {
                    uint32_t b0, b1, b2, b3;
                    int nbx = nbp * 2 + v_nh;
                    ldsm4t(b0, b1, b2, b3,
                           vab + vrow * 128 + ((nbx ^ v_sw) << 4));
                    mma16(o[nbp * 2],     a0, a1, a2, a3, b0, b1);
                    mma16(o[nbp * 2 + 1], a0, a1, a2, a3, b2, b3);
                }
            }
        }

        // ---- epilogue: write unnormalized partials ----
        l0 += __shfl_xor_sync(0xffffffffu, l0, 1);
        l0 += __shfl_xor_sync(0xffffffffu, l0, 2);
        l1 += __shfl_xor_sync(0xffffffffu, l1, 1);
        l1 += __shfl_xor_sync(0xffffffffu, l1, 2);

        const int sbase = (batch * 68 + slot) * 2 + group;
        float* po = g_po + (size_t)sbase * 4096;
        const int r0 = wr + g, r1 = wr + g + 8;
        #pragma unroll
        for (int nt = 0; nt < 8; nt++) {
            int cc = nt * 8 + 2 * tig;
            *(float2*)&po[r0 * 64 + cc] = make_float2(o[nt][0], o[nt][1]);
            *(float2*)&po[r1 * 64 + cc] = make_float2(o[nt][2], o[nt][3]);
        }
        if (tig == 0) {
            g_pl[sbase * 64 + r0] = l0;
            g_pl[sbase * 64 + r1] = l1;
        }
    }
}

// ---------------------------------------------------------------------------
// merge: out[tile] = sum(O partials) / sum(l partials).
// ---------------------------------------------------------------------------
__global__ __launch_bounds__(256) void merge_kernel(float* __restrict__ out)
{
    const int tile  = blockIdx.x >> 2;
    const int batch = tile >> 5;
    const int qt    = tile & 31;
    const int set   = qt >> 1;
    const int gg    = qt & 1;

    const int i4  = (blockIdx.x & 3) * 256 + threadIdx.x;
    const int row = i4 >> 4;
    const int d0  = (i4 & 15) << 2;

    float4 os = make_float4(0.f, 0.f, 0.f, 0.f);
    float ls = 0.f;
    #pragma unroll
    for (int i = 0; i < 4; i++) {
        int s = MSLOT[set][i];
        if (s >= 0) {
            int sbase = (batch * 68 + s) * 2 + gg;
            float4 v = *(const float4*)&g_po[(size_t)sbase * 4096 + row * 64 + d0];
            os.x += v.x; os.y += v.y; os.z += v.z; os.w += v.w;
            ls += g_pl[sbase * 64 + row];
        }
    }
    float inv = 1.f / ls;
    float4 w = make_float4(os.x * inv, os.y * inv, os.z * inv, os.w * inv);
    *(float4*)&out[((size_t)(batch * TT + qt * 64 + row)) * DD + d0] = w;
}

// ---------------------------------------------------------------------------
extern "C" void kernel_launch(void* const* d_in, const int* in_sizes, int n_in,
                              void* d_out, int out_size)
{
    const float* x  = (const float*)d_in[0];
    const float* Wk = (const float*)d_in[1];
    const float* Wq = (const float*)d_in[2];
    const float* Wv = (const float*)d_in[3];
    float* out = (float*)d_out;

    cudaFuncSetAttribute(w_prep,
                         cudaFuncAttributeMaxDynamicSharedMemorySize, WPREP_SMEM);
    cudaFuncSetAttribute(proj_kernel,
                         cudaFuncAttributeMaxDynamicSharedMemorySize, PROJ_SMEM);
    cudaFuncSetAttribute(attn_kernel,
                         cudaFuncAttributeMaxDynamicSharedMemorySize, ATTN_SMEM);

    w_prep<<<48, 256, WPREP_SMEM>>>(Wk, Wq, Wv);
    proj_kernel<<<dim3(128, 2), 256, PROJ_SMEM>>>(x);
    attn_kernel<<<8 * 34, 256, ATTN_SMEM>>>();
    merge_kernel<<<1024, 256>>>(out);
}

// round 17
// speedup vs baseline: 1.7261x; 1.0792x over previous
#include <cuda_runtime.h>
#include <math.h>
#include <stdint.h>

#define BB 8
#define TT 2048
#define HH 1024
#define DD 64
#define NTOK (BB*TT)   // 16384

// q pre-scaled by log2(e)/8 so attn uses ex2 directly.
#define QSCALE 0.1803368801111204f

__device__ uint32_t g_qh[NTOK*32];     // Q as packed fp16x2 (pre-scaled)
__device__ uint32_t g_kh[NTOK*32];     // K as packed fp16x2
__device__ uint32_t g_vb[NTOK*32];     // V as packed fp16x2
__device__ uint32_t g_wt[16 * 6144];   // W fp16, [chunk64][n][32 words], pre-swizzled

// split-k partial scratch (fp16x2): 8 batches x 68 slots x 2 tiles x 2048 words
__device__ uint32_t g_po[8 * 68 * 2 * 2048];
__device__ float    g_pl[8 * 68 * 2 * 64];

// ---- task tables: 34 blocks per batch, each exactly 8 k-iters, <=2 tasks.
__device__ __constant__ int T0SET[34] = {
    15,15,15,15, 14,14,14, 13,13,13, 12,12,12, 11,11,11,
    10,10, 9,9, 8,8, 7,7, 6, 5, 4, 3, 14, 10, 6, 2, 13, 5};
__device__ __constant__ int T0K0[34] = {
    0,8,16,24, 0,8,16, 0,8,16, 0,8,16, 0,8,16,
    0,8, 0,8, 0,8, 0,8, 0, 0, 0, 0, 24, 16, 8, 0, 24, 8};
__device__ __constant__ int T0K1[34] = {
    8,16,24,32, 8,16,24, 8,16,24, 8,16,24, 8,16,24,
    8,16, 8,16, 8,16, 8,16, 8, 8, 8, 8, 30, 22, 14, 6, 28, 12};
__device__ __constant__ int T1SET[34] = {
    -1,-1,-1,-1, -1,-1,-1, -1,-1,-1, -1,-1,-1, -1,-1,-1,
    -1,-1, -1,-1, -1,-1, -1,-1, -1, -1, -1, -1, 12, 8, 4, 0, 9, 1};
__device__ __constant__ int T1K0[34] = {
    0,0,0,0, 0,0,0, 0,0,0, 0,0,0, 0,0,0,
    0,0, 0,0, 0,0, 0,0, 0, 0, 0, 0, 24, 16, 8, 0, 16, 0};
__device__ __constant__ int T1K1[34] = {
    0,0,0,0, 0,0,0, 0,0,0, 0,0,0, 0,0,0,
    0,0, 0,0, 0,0, 0,0, 0, 0, 0, 0, 26, 18, 10, 2, 20, 4};

__device__ __constant__ int MSLOT[16][4] = {
    {63,-1,-1,-1}, {67,-1,-1,-1}, {62,-1,-1,-1}, {54,-1,-1,-1},
    {52,61,-1,-1}, {50,66,-1,-1}, {48,60,-1,-1}, {44,46,-1,-1},
    {40,42,59,-1}, {36,38,65,-1}, {32,34,58,-1}, {26,28,30,-1},
    {20,22,24,57}, {14,16,18,64}, {8,10,12,56},  {0,2,4,6}};

// ---------------------------------------------------------------------------
// helpers
// ---------------------------------------------------------------------------
__device__ __forceinline__ float ex2(float f) {
    float r; asm("ex2.approx.ftz.f32 %0, %1;" : "=f"(r) : "f"(f)); return r;
}

__device__ __forceinline__ uint32_t h2(float lo, float hi) {
    uint32_t r; asm("cvt.rn.f16x2.f32 %0, %1, %2;" : "=r"(r) : "f"(hi), "f"(lo));
    return r;
}

__device__ __forceinline__ float2 h2f(uint32_t h) {
    float2 r;
    asm("{ .reg .f16 lo, hi;\n\t"
        "mov.b32 {lo, hi}, %2;\n\t"
        "cvt.f32.f16 %0, lo;\n\t"
        "cvt.f32.f16 %1, hi; }"
        : "=f"(r.x), "=f"(r.y) : "r"(h));
    return r;
}

__device__ __forceinline__ void mma16(float c[4],
    uint32_t a0, uint32_t a1, uint32_t a2, uint32_t a3,
    uint32_t b0, uint32_t b1)
{
    asm volatile(
        "mma.sync.aligned.m16n8k16.row.col.f32.f16.f16.f32 "
        "{%0,%1,%2,%3}, {%4,%5,%6,%7}, {%8,%9}, {%0,%1,%2,%3};"
        : "+f"(c[0]), "+f"(c[1]), "+f"(c[2]), "+f"(c[3])
        : "r"(a0), "r"(a1), "r"(a2), "r"(a3), "r"(b0), "r"(b1));
}

__device__ __forceinline__ void ldsm4(uint32_t& r0, uint32_t& r1,
                                      uint32_t& r2, uint32_t& r3, uint32_t addr)
{
    asm volatile("ldmatrix.sync.aligned.m8n8.x4.shared.b16 {%0,%1,%2,%3}, [%4];"
        : "=r"(r0), "=r"(r1), "=r"(r2), "=r"(r3) : "r"(addr));
}

__device__ __forceinline__ void ldsm4t(uint32_t& r0, uint32_t& r1,
                                       uint32_t& r2, uint32_t& r3, uint32_t addr)
{
    asm volatile("ldmatrix.sync.aligned.m8n8.x4.trans.shared.b16 {%0,%1,%2,%3}, [%4];"
        : "=r"(r0), "=r"(r1), "=r"(r2), "=r"(r3) : "r"(addr));
}

__device__ __forceinline__ void cpa16(uint32_t saddr, const void* g) {
    asm volatile("cp.async.cg.shared.global [%0], [%1], 16;" :: "r"(saddr), "l"(g));
}
#define CPA_COMMIT asm volatile("cp.async.commit_group;")
#define CPA_WAIT0  asm volatile("cp.async.wait_group 0;")

// ---------------------------------------------------------------------------
// w_prep: W -> fp16 pre-swizzled (k-chunk 64, 128B rows). 48 blocks x 256 thr,
// coalesced loads staged via transposed smem.
// ---------------------------------------------------------------------------
#define WPREP_SMEM 69632

__global__ __launch_bounds__(256) void w_prep(
    const float* __restrict__ Wk,
    const float* __restrict__ Wq,
    const float* __restrict__ Wv)
{
    extern __shared__ float sW[];   // sW[col][68]
    const int t = threadIdx.x;
    const int chunk = blockIdx.x / 3;
    const int m = blockIdx.x % 3;
    const float* W = (m == 0) ? Wq : (m == 1) ? Wk : Wv;
    const int k0 = chunk * 64;
    const int nbase = m * 64;

    #pragma unroll
    for (int i = 0; i < 4; i++) {
        int idx = t + i * 256;
        int r = idx >> 4, c4 = idx & 15;
        float4 v = *(const float4*)&W[(size_t)(k0 + r) * DD + c4 * 4];
        sW[(c4 * 4 + 0) * 68 + r] = v.x;
        sW[(c4 * 4 + 1) * 68 + r] = v.y;
        sW[(c4 * 4 + 2) * 68 + r] = v.z;
        sW[(c4 * 4 + 3) * 68 + r] = v.w;
    }
    __syncthreads();

    #pragma unroll
    for (int i = 0; i < 2; i++) {
        int task = t + i * 256;
        int ncol = task >> 3, c4 = task & 7;
        const float* src = &sW[ncol * 68 + c4 * 8];
        float4 lo = *(const float4*)src;
        float4 hi = *(const float4*)(src + 4);
        uint4 v;
        v.x = h2(lo.x, lo.y);
        v.y = h2(lo.z, lo.w);
        v.z = h2(hi.x, hi.y);
        v.w = h2(hi.z, hi.w);
        int n = nbase + ncol;
        *(uint4*)&g_wt[chunk * 6144 + n * 32 + ((c4 ^ (n & 7)) << 2)] = v;
    }
}

// ---------------------------------------------------------------------------
// Fused projection, all-fp16 mma16, SINGLE PASS over x.
// Grid 256: block tile M=64, N=192. 256 threads = 8 warps (2m x 4n),
// warp tile 32m x 48n. k-chunk 64.
// smem bytes: xs32 @0 (16K fp32 staging), xh dbl @16384 (2x8K),
//             W dbl @32768 (2x24K). Total 81920 -> 2 blocks/SM.
// ---------------------------------------------------------------------------
#define PROJ_SMEM 81920

__global__ __launch_bounds__(256, 2) void proj_kernel(const float* __restrict__ x)
{
    extern __shared__ uint32_t psm[];
    const uint32_t sb = (uint32_t)__cvta_generic_to_shared(psm);

    const int t    = threadIdx.x;
    const int lane = t & 31;
    const int warp = t >> 5;
    const int g    = lane >> 2;
    const int tig  = lane & 3;
    const int warpM = warp & 1;    // 0..1
    const int warpN = warp >> 1;   // 0..3
    const int row0 = blockIdx.x * 64;

    float acc[2][6][4];
    #pragma unroll
    for (int a = 0; a < 2; a++)
        #pragma unroll
        for (int j = 0; j < 6; j++)
            #pragma unroll
            for (int e = 0; e < 4; e++) acc[a][j][e] = 0.f;

    const int arow0 = warpM * 32 + ((lane >> 3) & 1) * 8 + (lane & 7);
    const int a_kh  = (lane >> 4) & 1;
    const int brow0 = warpN * 48 + ((lane >> 4) & 1) * 8 + (lane & 7);
    const int k_kh  = (lane >> 3) & 1;

    auto load_x = [&](int c) {
        const float* xsrc = x + (size_t)row0 * HH + c * 64;
        #pragma unroll
        for (int i = 0; i < 4; i++) {
            int task = t + i * 256;
            int r = task >> 4, c4 = task & 15;
            cpa16(sb + r * 256 + c4 * 16, xsrc + (size_t)r * HH + c4 * 4);
        }
    };
    auto load_w = [&](int c) {
        uint32_t wb = sb + 32768 + (c & 1) * 24576;
        const uint32_t* wsrc = g_wt + c * 6144;
        #pragma unroll
        for (int i = 0; i < 6; i++) {
            int task = t + i * 256;
            cpa16(wb + task * 16, wsrc + task * 4);
        }
    };

    load_x(0);
    load_w(0);
    CPA_COMMIT;

    for (int c = 0; c < 16; c++) {
        CPA_WAIT0;
        __syncthreads();   // xs32(c), W(c) visible; prev xh reads done

        // convert xs32 (fp32) -> xh[c&1] (fp16, 128B rows, chunk XOR (r&7))
        uint32_t* xh = psm + (16384 + (c & 1) * 8192) / 4;
        #pragma unroll
        for (int i = 0; i < 4; i++) {
            int task = t + i * 256;
            int r = task >> 4, c4 = task & 15;
            float4 v = *(const float4*)&psm[r * 64 + c4 * 4];
            uint32_t w0 = h2(v.x, v.y), w1 = h2(v.z, v.w);
            int idx = r * 32 + (((c4 >> 1) ^ (r & 7)) << 2) + (c4 & 1) * 2;
            *(uint2*)&xh[idx] = make_uint2(w0, w1);
        }
        __syncthreads();   // xh visible; xs32 free

        if (c + 1 < 16) {
            load_x(c + 1);
            load_w(c + 1);
            CPA_COMMIT;
        }

        const uint32_t xb = sb + 16384 + (c & 1) * 8192;
        const uint32_t wb = sb + 32768 + (c & 1) * 24576;

        #pragma unroll
        for (int kb = 0; kb < 4; kb++) {
            uint32_t a[2][4];
            #pragma unroll
            for (int mt = 0; mt < 2; mt++) {
                int ar = arow0 + mt * 16;
                ldsm4(a[mt][0], a[mt][1], a[mt][2], a[mt][3],
                      xb + ar * 128 + (((2 * kb + a_kh) ^ (ar & 7)) << 4));
            }
            #pragma unroll
            for (int p = 0; p < 3; p++) {
                int br = brow0 + p * 16;
                uint32_t b0, b1, b2, b3;
                ldsm4(b0, b1, b2, b3,
                      wb + br * 128 + (((2 * kb + k_kh) ^ (br & 7)) << 4));
                mma16(acc[0][2 * p],     a[0][0], a[0][1], a[0][2], a[0][3], b0, b1);
                mma16(acc[0][2 * p + 1], a[0][0], a[0][1], a[0][2], a[0][3], b2, b3);
                mma16(acc[1][2 * p],     a[1][0], a[1][1], a[1][2], a[1][3], b0, b1);
                mma16(acc[1][2 * p + 1], a[1][0], a[1][1], a[1][2], a[1][3], b2, b3);
            }
        }
    }

    #pragma unroll
    for (int mt = 0; mt < 2; mt++) {
        int r = row0 + warpM * 32 + mt * 16 + g;
        #pragma unroll
        for (int j = 0; j < 6; j++) {
            int nb = warpN * 48 + j * 8;
            int w = ((nb & 63) >> 1) + tig;
            uint32_t* o = (nb < 64) ? g_qh : (nb < 128) ? g_kh : g_vb;
            float sc = (nb < 64) ? QSCALE : 1.0f;
            o[(size_t)r       * 32 + w] = h2(acc[mt][j][0] * sc, acc[mt][j][1] * sc);
            o[(size_t)(r + 8) * 32 + w] = h2(acc[mt][j][2] * sc, acc[mt][j][3] * sc);
        }
    }
}

// ---------------------------------------------------------------------------
// Attention (all-fp16, register-fragment PV): 272 blocks x 256 threads
// (2 groups), 2 blocks/SM, 8 k-iters each. Partials stored as fp16x2.
// smem bytes: qs[g]@g*8192, K dbl @16384, V dbl @32768. Total 48KB.
// ---------------------------------------------------------------------------
#define ATTN_SMEM 49152

__device__ __forceinline__ void cpa_htile128(uint32_t sbase_b, const uint32_t* gsrc, int lt) {
    #pragma unroll
    for (int i = 0; i < 4; i++) {
        int task = lt + i * 128;
        int r = task >> 3, c4 = task & 7;
        cpa16(sbase_b + r * 128 + ((c4 ^ (r & 7)) << 4), gsrc + r * 32 + c4 * 4);
    }
}
__device__ __forceinline__ void cpa_htile256(uint32_t sbase_b, const uint32_t* gsrc, int tid) {
    #pragma unroll
    for (int i = 0; i < 2; i++) {
        int task = tid + i * 256;
        int r = task >> 3, c4 = task & 7;
        cpa16(sbase_b + r * 128 + ((c4 ^ (r & 7)) << 4), gsrc + r * 32 + c4 * 4);
    }
}

__global__ __launch_bounds__(256, 2) void attn_kernel()
{
    extern __shared__ uint32_t sm[];
    const uint32_t base = (uint32_t)__cvta_generic_to_shared(sm);

    const int tid   = threadIdx.x;
    const int group = tid >> 7;
    const int lt    = tid & 127;
    const int lane  = tid & 31;
    const int warpg = lt >> 5;
    const int g     = lane >> 2;
    const int tig   = lane & 3;
    const int wr    = warpg * 16;
    const int batch = blockIdx.x / 34;
    const int bb    = blockIdx.x % 34;

    const uint32_t qb = base + group * 8192;

    const int qrow = wr + ((lane >> 3) & 1) * 8 + (lane & 7);
    const uint32_t qab = qb + qrow * 128;
    const int q_kh = (lane >> 4) & 1, q_sw = qrow & 7;
    const int krlo = ((lane >> 4) & 1) * 8 + (lane & 7);
    const int k_kh = (lane >> 3) & 1;
    const int vrlo = (lane & 7) + ((lane >> 3) & 1) * 8;
    const int v_nh = (lane >> 4) & 1;
    const int v_sw = vrlo & 7;

    const size_t kvoff = (size_t)batch * TT * 32;

    #pragma unroll 1
    for (int task = 0; task < 2; task++) {
        int set, k0t, k1t;
        if (task == 0) { set = T0SET[bb]; k0t = T0K0[bb]; k1t = T0K1[bb]; }
        else           { set = T1SET[bb]; k0t = T1K0[bb]; k1t = T1K1[bb];
                         if (set < 0) break; }
        const int qt   = set * 2 + group;
        const int slot = bb * 2 + task;

        __syncthreads();

        cpa_htile128(qb, g_qh + kvoff + (size_t)qt * 64 * 32, lt);
        cpa_htile256(base + 16384 + (k0t & 1) * 8192,
                     g_kh + kvoff + (size_t)k0t * 64 * 32, tid);
        cpa_htile256(base + 32768 + (k0t & 1) * 8192,
                     g_vb + kvoff + (size_t)k0t * 64 * 32, tid);
        CPA_COMMIT;

        float l0 = 0.f, l1 = 0.f;
        float o[8][4];
        #pragma unroll
        for (int nt = 0; nt < 8; nt++)
            #pragma unroll
            for (int e = 0; e < 4; e++) o[nt][e] = 0.f;

        for (int kt = k0t; kt < k1t; kt++) {
            CPA_WAIT0;
            __syncthreads();

            if (kt + 1 < k1t) {
                cpa_htile256(base + 16384 + ((kt + 1) & 1) * 8192,
                             g_kh + kvoff + (size_t)(kt + 1) * 64 * 32, tid);
                cpa_htile256(base + 32768 + ((kt + 1) & 1) * 8192,
                             g_vb + kvoff + (size_t)(kt + 1) * 64 * 32, tid);
                CPA_COMMIT;
            }

            const uint32_t kab = base + 16384 + (kt & 1) * 8192;
            const uint32_t vab = base + 32768 + (kt & 1) * 8192;

            float s[8][4];
            #pragma unroll
            for (int nt = 0; nt < 8; nt++)
                #pragma unroll
                for (int e = 0; e < 4; e++) s[nt][e] = 0.f;

            #pragma unroll
            for (int kb = 0; kb < 4; kb++) {
                uint32_t a0, a1, a2, a3;
                ldsm4(a0, a1, a2, a3, qab + (((2 * kb + q_kh) ^ q_sw) << 4));
                #pragma unroll
                for (int p = 0; p < 4; p++) {
                    int kr = p * 16 + krlo;
                    uint32_t b0, b1, b2, b3;
                    ldsm4(b0, b1, b2, b3,
                          kab + kr * 128 + (((2 * kb + k_kh) ^ (kr & 7)) << 4));
                    mma16(s[2 * p],     a0, a1, a2, a3, b0, b1);
                    mma16(s[2 * p + 1], a0, a1, a2, a3, b2, b3);
                }
            }

            const int r0 = wr + g, r1 = wr + g + 8;
            if (kt >= qt) {
                const int gr0 = (qt << 6) + r0, gr1 = (qt << 6) + r1;
                #pragma unroll
                for (int nt = 0; nt < 8; nt++) {
                    int gc = (kt << 6) + nt * 8 + 2 * tig;
                    if (gc     > gr0) s[nt][0] = -INFINITY;
                    if (gc + 1 > gr0) s[nt][1] = -INFINITY;
                    if (gc     > gr1) s[nt][2] = -INFINITY;
                    if (gc + 1 > gr1) s[nt][3] = -INFINITY;
                }
            }
            #pragma unroll
            for (int nt = 0; nt < 8; nt++) {
                s[nt][0] = ex2(s[nt][0]);
                s[nt][1] = ex2(s[nt][1]);
                s[nt][2] = ex2(s[nt][2]);
                s[nt][3] = ex2(s[nt][3]);
                l0 += s[nt][0] + s[nt][1];
                l1 += s[nt][2] + s[nt][3];
            }

            #pragma unroll
            for (int kb = 0; kb < 4; kb++) {
                uint32_t a0 = h2(s[2 * kb][0],     s[2 * kb][1]);
                uint32_t a1 = h2(s[2 * kb][2],     s[2 * kb][3]);
                uint32_t a2 = h2(s[2 * kb + 1][0], s[2 * kb + 1][1]);
                uint32_t a3 = h2(s[2 * kb + 1][2], s[2 * kb + 1][3]);
                int vrow = kb * 16 + vrlo;
                #pragma unroll
                for (int nbp = 0; nbp < 4; nbp++) {
                    uint32_t b0, b1, b2, b3;
                    int nbx = nbp * 2 + v_nh;
                    ldsm4t(b0, b1, b2, b3,
                           vab + vrow * 128 + ((nbx ^ v_sw) << 4));
                    mma16(o[nbp * 2],     a0, a1, a2, a3, b0, b1);
                    mma16(o[nbp * 2 + 1], a0, a1, a2, a3, b2, b3);
                }
            }
        }

        // ---- epilogue: write unnormalized partials (fp16x2) ----
        l0 += __shfl_xor_sync(0xffffffffu, l0, 1);
        l0 += __shfl_xor_sync(0xffffffffu, l0, 2);
        l1 += __shfl_xor_sync(0xffffffffu, l1, 1);
        l1 += __shfl_xor_sync(0xffffffffu, l1, 2);

        const int sbase = (batch * 68 + slot) * 2 + group;
        uint32_t* po = g_po + (size_t)sbase * 2048;
        const int r0 = wr + g, r1 = wr + g + 8;
        #pragma unroll
        for (int nt = 0; nt < 8; nt++) {
            int w = nt * 4 + tig;   // cc/2
            po[r0 * 32 + w] = h2(o[nt][0], o[nt][1]);
            po[r1 * 32 + w] = h2(o[nt][2], o[nt][3]);
        }
        if (tig == 0) {
            g_pl[sbase * 64 + r0] = l0;
            g_pl[sbase * 64 + r1] = l1;
        }
    }
}

// ---------------------------------------------------------------------------
// merge: out[tile] = sum(O partials fp16) / sum(l partials).
// 1024 blocks x 256 threads, one 4-col group per thread.
// ---------------------------------------------------------------------------
__global__ __launch_bounds__(256) void merge_kernel(float* __restrict__ out)
{
    const int tile  = blockIdx.x >> 2;
    const int batch = tile >> 5;
    const int qt    = tile & 31;
    const int set   = qt >> 1;
    const int gg    = qt & 1;

    const int i4  = (blockIdx.x & 3) * 256 + threadIdx.x;
    const int row = i4 >> 4;
    const int d0  = (i4 & 15) << 2;

    float4 os = make_float4(0.f, 0.f, 0.f, 0.f);
    float ls = 0.f;
    #pragma unroll
    for (int i = 0; i < 4; i++) {
        int s = MSLOT[set][i];
        if (s >= 0) {
            int sbase = (batch * 68 + s) * 2 + gg;
            uint2 pw = *(const uint2*)&g_po[(size_t)sbase * 2048 + row * 32 + (d0 >> 1)];
            float2 a = h2f(pw.x), b = h2f(pw.y);
            os.x += a.x; os.y += a.y; os.z += b.x; os.w += b.y;
            ls += g_pl[sbase * 64 + row];
        }
    }
    float inv = 1.f / ls;
    float4 w = make_float4(os.x * inv, os.y * inv, os.z * inv, os.w * inv);
    *(float4*)&out[((size_t)(batch * TT + qt * 64 + row)) * DD + d0] = w;
}

// ---------------------------------------------------------------------------
extern "C" void kernel_launch(void* const* d_in, const int* in_sizes, int n_in,
                              void* d_out, int out_size)
{
    const float* x  = (const float*)d_in[0];
    const float* Wk = (const float*)d_in[1];
    const float* Wq = (const float*)d_in[2];
    const float* Wv = (const float*)d_in[3];
    float* out = (float*)d_out;

    cudaFuncSetAttribute(w_prep,
                         cudaFuncAttributeMaxDynamicSharedMemorySize, WPREP_SMEM);
    cudaFuncSetAttribute(proj_kernel,
                         cudaFuncAttributeMaxDynamicSharedMemorySize, PROJ_SMEM);
    cudaFuncSetAttribute(attn_kernel,
                         cudaFuncAttributeMaxDynamicSharedMemorySize, ATTN_SMEM);

    w_prep<<<48, 256, WPREP_SMEM>>>(Wk, Wq, Wv);
    proj_kernel<<<NTOK / 64, 256, PROJ_SMEM>>>(x);
    attn_kernel<<<8 * 34, 256, ATTN_SMEM>>>();
    merge_kernel<<<1024, 256>>>(out);
}